// round 4
// baseline (speedup 1.0000x reference)
#include <cuda_runtime.h>

// Problem constants
#define D 128
#define NMAX 50000
#define EMAX 1600000

// Scratch — float4 arrays guarantee 16B alignment for vector LDG/STG.
__device__ float4 g_B0[NMAX * 32];   // h*dinv (pre-scaled linear output)
__device__ float4 g_B1[NMAX * 32];   // scatter accumulator
__device__ float4 g_B2[NMAX * 32];   // layer activation
__device__ float  g_deg[NMAX];
__device__ float  g_dinv[NMAX];
__device__ int    g_src[EMAX];
__device__ int    g_dst[EMAX];
__device__ int    g_is64;

// ---------------------------------------------------------------------------
// Detect edge_index dtype: if int64, the odd 32-bit words are high halves of
// small non-negative values -> all zero. If int32, they are random indices.
__global__ void k_detect(const unsigned int* __restrict__ p, int* flag) {
    __shared__ unsigned int s;
    if (threadIdx.x == 0) s = 0u;
    __syncthreads();
    unsigned int v = p[threadIdx.x * 2 + 1];   // 256 odd words within first 2KB
    #pragma unroll
    for (int o = 16; o >= 1; o >>= 1) v |= __shfl_xor_sync(0xffffffffu, v, o);
    if ((threadIdx.x & 31) == 0) atomicOr(&s, v);
    __syncthreads();
    if (threadIdx.x == 0) *flag = (s == 0u) ? 1 : 0;
}

// Decode edge_index (either dtype) into int arrays.
__global__ void k_convert(const void* __restrict__ ei, const int* __restrict__ flag,
                          int* __restrict__ src, int* __restrict__ dst, int e) {
    int i = blockIdx.x * blockDim.x + threadIdx.x;
    if (i >= e) return;
    if (*flag) {
        const long long* p = (const long long*)ei;
        src[i] = (int)p[i];
        dst[i] = (int)p[e + i];
    } else {
        const int* p = (const int*)ei;
        src[i] = p[i];
        dst[i] = p[e + i];
    }
}

// ---------------------------------------------------------------------------
__global__ void k_init_deg(float* deg, int n) {
    int i = blockIdx.x * blockDim.x + threadIdx.x;
    if (i < n) deg[i] = 1.0f;   // self-loop
}

__global__ void k_count(const int* __restrict__ dst, float* deg, int e) {
    int i = blockIdx.x * blockDim.x + threadIdx.x;
    if (i < e) atomicAdd(&deg[dst[i]], 1.0f);
}

__global__ void k_dinv(const float* __restrict__ deg, float* dinv, int n) {
    int i = blockIdx.x * blockDim.x + threadIdx.x;
    if (i < n) dinv[i] = rsqrtf(deg[i]);
}

__global__ void k_zero(float4* p, int n4) {
    int i = blockIdx.x * blockDim.x + threadIdx.x;
    if (i < n4) p[i] = make_float4(0.f, 0.f, 0.f, 0.f);
}

// ---------------------------------------------------------------------------
// C[m][0:128] = (sum_k A[m][k] * W[k][n]) * scale[m]
// Block: 128 rows x 128 cols, 256 threads, 8x8 register tile per thread.
__global__ void __launch_bounds__(256, 1)
k_gemm128(const float4* __restrict__ A, const float* __restrict__ W,
          const float* __restrict__ scale, float4* __restrict__ C, int n)
{
    extern __shared__ float sm[];
    float* xs = sm;                 // [128][132]
    float* ws = sm + 128 * 132;     // [128][128]
    const int m0 = blockIdx.x * 128;
    const int t  = threadIdx.x;

    #pragma unroll
    for (int i = 0; i < 16; i++) {
        int idx = t + 256 * i;      // float4 index into 128x128 W
        ((float4*)ws)[idx] = ((const float4*)W)[idx];
    }
    #pragma unroll
    for (int i = 0; i < 16; i++) {
        int idx = t + 256 * i;      // float4 index into A tile
        int m = idx >> 5, k4 = idx & 31;
        float4 v = make_float4(0.f, 0.f, 0.f, 0.f);
        if (m0 + m < n) v = A[(size_t)(m0 + m) * 32 + k4];
        *(float4*)(xs + m * 132 + k4 * 4) = v;
    }
    __syncthreads();

    const int tcol = t & 15, trow = t >> 4;
    float acc[8][8];
    #pragma unroll
    for (int r = 0; r < 8; r++)
        #pragma unroll
        for (int c = 0; c < 8; c++) acc[r][c] = 0.f;

    const float* xb = xs + trow * 8 * 132;
    #pragma unroll 8
    for (int k = 0; k < 128; k++) {
        float4 b0 = *(const float4*)(ws + k * 128 + tcol * 4);
        float4 b1 = *(const float4*)(ws + k * 128 + 64 + tcol * 4);
        float b[8] = {b0.x, b0.y, b0.z, b0.w, b1.x, b1.y, b1.z, b1.w};
        #pragma unroll
        for (int r = 0; r < 8; r++) {
            float a = xb[r * 132 + k];
            #pragma unroll
            for (int c = 0; c < 8; c++) acc[r][c] = fmaf(a, b[c], acc[r][c]);
        }
    }

    #pragma unroll
    for (int r = 0; r < 8; r++) {
        int m = m0 + trow * 8 + r;
        if (m < n) {
            float s = scale[m];
            C[(size_t)m * 32 + tcol]      = make_float4(acc[r][0]*s, acc[r][1]*s, acc[r][2]*s, acc[r][3]*s);
            C[(size_t)m * 32 + 16 + tcol] = make_float4(acc[r][4]*s, acc[r][5]*s, acc[r][6]*s, acc[r][7]*s);
        }
    }
}

// ---------------------------------------------------------------------------
// One warp per edge: agg[dst] += h[src] (128 floats)
__global__ void k_scatter(const float4* __restrict__ h,
                          const int* __restrict__ src,
                          const int* __restrict__ dst,
                          float4* __restrict__ agg, int e)
{
    int w = (blockIdx.x * 256 + threadIdx.x) >> 5;
    int lane = threadIdx.x & 31;
    if (w >= e) return;
    int s = __ldg(&src[w]);
    int d = __ldg(&dst[w]);
    float4 v = h[(size_t)s * 32 + lane];
    float* a = (float*)&agg[(size_t)d * 32 + lane];
    atomicAdd(a + 0, v.x);
    atomicAdd(a + 1, v.y);
    atomicAdd(a + 2, v.z);
    atomicAdd(a + 3, v.w);
}

// ---------------------------------------------------------------------------
// out[i][c] = act((agg[i][c] + hs[i][c]) * dinv[i] + b[c])
__global__ void k_post(const float4* __restrict__ agg, const float4* __restrict__ hs,
                       const float* __restrict__ dinv, const float* __restrict__ b,
                       float4* __restrict__ out, int n, int relu)
{
    int i = blockIdx.x * blockDim.x + threadIdx.x;   // float4 index
    if (i >= n * 32) return;
    int row = i >> 5, c4 = i & 31;
    float s = dinv[row];
    float4 a = agg[i];
    float4 h = hs[i];
    const float* bp = b + c4 * 4;
    float4 r;
    r.x = (a.x + h.x) * s + bp[0];
    r.y = (a.y + h.y) * s + bp[1];
    r.z = (a.z + h.z) * s + bp[2];
    r.w = (a.w + h.w) * s + bp[3];
    if (relu) {
        r.x = fmaxf(r.x, 0.f); r.y = fmaxf(r.y, 0.f);
        r.z = fmaxf(r.z, 0.f); r.w = fmaxf(r.w, 0.f);
    }
    out[i] = r;
}

// ---------------------------------------------------------------------------
// out = softmax(H @ Wa + ba) over K=100 cols (padded to 128 in smem)
__global__ void __launch_bounds__(256, 1)
k_final(const float4* __restrict__ H, const float* __restrict__ Wa,
        const float* __restrict__ ba, float* __restrict__ out, int n)
{
    extern __shared__ float sm[];
    float* hs  = sm;                  // [128][132]
    float* was = sm + 128 * 132;      // [128][128] zero-padded
    float* bas = was + 128 * 128;     // [128]
    const int m0 = blockIdx.x * 128;
    const int t  = threadIdx.x;

    #pragma unroll
    for (int i = 0; i < 64; i++) {
        int idx = t + 256 * i;        // scalar index into 128x128
        int k = idx >> 7, c = idx & 127;
        was[idx] = (c < 100) ? Wa[k * 100 + c] : 0.f;
    }
    if (t < 128) bas[t] = (t < 100) ? ba[t] : -1e30f;
    #pragma unroll
    for (int i = 0; i < 16; i++) {
        int idx = t + 256 * i;
        int m = idx >> 5, k4 = idx & 31;
        float4 v = make_float4(0.f, 0.f, 0.f, 0.f);
        if (m0 + m < n) v = H[(size_t)(m0 + m) * 32 + k4];
        *(float4*)(hs + m * 132 + k4 * 4) = v;
    }
    __syncthreads();

    const int tcol = t & 15, trow = t >> 4;
    float acc[8][8];
    #pragma unroll
    for (int r = 0; r < 8; r++)
        #pragma unroll
        for (int c = 0; c < 8; c++) acc[r][c] = 0.f;

    const float* xb = hs + trow * 8 * 132;
    #pragma unroll 8
    for (int k = 0; k < 128; k++) {
        float4 b0 = *(const float4*)(was + k * 128 + tcol * 4);
        float4 b1 = *(const float4*)(was + k * 128 + 64 + tcol * 4);
        float b[8] = {b0.x, b0.y, b0.z, b0.w, b1.x, b1.y, b1.z, b1.w};
        #pragma unroll
        for (int r = 0; r < 8; r++) {
            float a = xb[r * 132 + k];
            #pragma unroll
            for (int c = 0; c < 8; c++) acc[r][c] = fmaf(a, b[c], acc[r][c]);
        }
    }

    float bv[8];
    #pragma unroll
    for (int c = 0; c < 4; c++) bv[c]     = bas[tcol * 4 + c];
    #pragma unroll
    for (int c = 0; c < 4; c++) bv[4 + c] = bas[64 + tcol * 4 + c];

    #pragma unroll
    for (int r = 0; r < 8; r++) {
        float v[8];
        #pragma unroll
        for (int c = 0; c < 8; c++) v[c] = acc[r][c] + bv[c];
        float mx = v[0];
        #pragma unroll
        for (int c = 1; c < 8; c++) mx = fmaxf(mx, v[c]);
        #pragma unroll
        for (int o = 8; o >= 1; o >>= 1)
            mx = fmaxf(mx, __shfl_xor_sync(0xffffffffu, mx, o));
        float sum = 0.f;
        #pragma unroll
        for (int c = 0; c < 8; c++) { v[c] = expf(v[c] - mx); sum += v[c]; }
        #pragma unroll
        for (int o = 8; o >= 1; o >>= 1)
            sum += __shfl_xor_sync(0xffffffffu, sum, o);
        float inv = 1.0f / sum;

        int m = m0 + trow * 8 + r;
        if (m < n) {
            *(float4*)(out + (size_t)m * 100 + tcol * 4) =
                make_float4(v[0]*inv, v[1]*inv, v[2]*inv, v[3]*inv);
            if (tcol < 9)
                *(float4*)(out + (size_t)m * 100 + 64 + tcol * 4) =
                    make_float4(v[4]*inv, v[5]*inv, v[6]*inv, v[7]*inv);
        }
    }
}

// ---------------------------------------------------------------------------
extern "C" void kernel_launch(void* const* d_in, const int* in_sizes, int n_in,
                              void* d_out, int out_size)
{
    // Resolve inputs by element count (robust to metadata ordering):
    int ix = 0, ie = 1, iW1 = 2, ib1 = 3, iW2 = 4, ib2 = 5, iWa = 6, iba = 7;
    {
        int jx=-1, je=-1, jW1=-1, jW2=-1, jb1=-1, jb2=-1, jWa=-1, jba=-1;
        for (int i = 0; i < n_in; i++) {
            int s = in_sizes[i];
            if      (s == 6400000) jx = i;
            else if (s == 3200000) je = i;
            else if (s == 16384)   { if (jW1 < 0) jW1 = i; else jW2 = i; }
            else if (s == 128)     { if (jb1 < 0) jb1 = i; else jb2 = i; }
            else if (s == 12800)   jWa = i;
            else if (s == 100)     jba = i;
        }
        if (jx>=0 && je>=0 && jW1>=0 && jW2>=0 && jb1>=0 && jb2>=0 && jWa>=0 && jba>=0) {
            ix=jx; ie=je; iW1=jW1; iW2=jW2; ib1=jb1; ib2=jb2; iWa=jWa; iba=jba;
        }
    }

    const float4* x   = (const float4*)d_in[ix];
    const void*   ei  = d_in[ie];
    const float*  W1  = (const float*)d_in[iW1];
    const float*  b1  = (const float*)d_in[ib1];
    const float*  W2  = (const float*)d_in[iW2];
    const float*  b2  = (const float*)d_in[ib2];
    const float*  Wa  = (const float*)d_in[iWa];
    const float*  ba  = (const float*)d_in[iba];
    float*        out = (float*)d_out;

    const int n = in_sizes[ix] / D;       // 50000
    const int e = in_sizes[ie] / 2;       // 1600000

    float4 *B0, *B1, *B2;
    float *deg, *dinv;
    int *srcI, *dstI, *is64;
    cudaGetSymbolAddress((void**)&B0, g_B0);
    cudaGetSymbolAddress((void**)&B1, g_B1);
    cudaGetSymbolAddress((void**)&B2, g_B2);
    cudaGetSymbolAddress((void**)&deg, g_deg);
    cudaGetSymbolAddress((void**)&dinv, g_dinv);
    cudaGetSymbolAddress((void**)&srcI, g_src);
    cudaGetSymbolAddress((void**)&dstI, g_dst);
    cudaGetSymbolAddress((void**)&is64, g_is64);

    const int SMEM_GEMM  = (128 * 132 + 128 * 128) * 4;
    const int SMEM_FINAL = (128 * 132 + 128 * 128 + 128) * 4;
    cudaFuncSetAttribute(k_gemm128, cudaFuncAttributeMaxDynamicSharedMemorySize, SMEM_GEMM);
    cudaFuncSetAttribute(k_final,  cudaFuncAttributeMaxDynamicSharedMemorySize, SMEM_FINAL);

    const int gemm_blocks = (n + 127) / 128;
    const int n4 = n * 32;
    const int zb = (n4 + 255) / 256;
    const int sb = (e + 7) / 8;                 // 8 warps/block, 1 warp/edge
    const int eb = (e + 255) / 256;

    // decode edge index (dtype-robust)
    k_detect<<<1, 256>>>((const unsigned int*)ei, is64);
    k_convert<<<eb, 256>>>(ei, is64, srcI, dstI, e);

    // degrees
    k_init_deg<<<(n + 255) / 256, 256>>>(deg, n);
    k_count<<<eb, 256>>>(dstI, deg, e);
    k_dinv<<<(n + 255) / 256, 256>>>(deg, dinv, n);

    // layer 1
    k_gemm128<<<gemm_blocks, 256, SMEM_GEMM>>>(x, W1, dinv, B0, n);
    k_zero<<<zb, 256>>>(B1, n4);
    k_scatter<<<sb, 256>>>(B0, srcI, dstI, B1, e);
    k_post<<<zb, 256>>>(B1, B0, dinv, b1, B2, n, 1);

    // layer 2
    k_gemm128<<<gemm_blocks, 256, SMEM_GEMM>>>(B2, W2, dinv, B0, n);
    k_zero<<<zb, 256>>>(B1, n4);
    k_scatter<<<sb, 256>>>(B0, srcI, dstI, B1, e);
    k_post<<<zb, 256>>>(B1, B0, dinv, b2, B2, n, 0);

    // head + softmax
    k_final<<<gemm_blocks, 256, SMEM_FINAL>>>(B2, Wa, ba, out, n);
}

// round 5
// speedup vs baseline: 3.2562x; 3.2562x over previous
#include <cuda_runtime.h>

// Problem constants
#define D 128
#define NMAX 50000
#define EMAX 1600000

// Scratch — float4 arrays guarantee 16B alignment for vector LDG/STG.
__device__ float4 g_B0[NMAX * 32];   // pre-scaled linear output (h * dinv[row])
__device__ float4 g_B2[NMAX * 32];   // layer activation
__device__ float  g_dinv[NMAX];
__device__ int    g_cnt[NMAX];       // incoming-edge counts
__device__ int    g_rowptr[NMAX + 1];
__device__ int    g_cursor[NMAX];
__device__ int    g_src[EMAX];
__device__ int    g_dst[EMAX];
__device__ int    g_adj[EMAX];       // CSR adjacency (src ids grouped by dst)
__device__ int    g_is64;

// ---------------------------------------------------------------------------
// Detect edge_index dtype: if int64, odd 32-bit words are high halves of
// small non-negative values -> all zero. If int32, they are random indices.
__global__ void k_detect(const unsigned int* __restrict__ p, int* flag) {
    __shared__ unsigned int s;
    if (threadIdx.x == 0) s = 0u;
    __syncthreads();
    unsigned int v = p[threadIdx.x * 2 + 1];
    #pragma unroll
    for (int o = 16; o >= 1; o >>= 1) v |= __shfl_xor_sync(0xffffffffu, v, o);
    if ((threadIdx.x & 31) == 0) atomicOr(&s, v);
    __syncthreads();
    if (threadIdx.x == 0) *flag = (s == 0u) ? 1 : 0;
}

__global__ void k_convert(const void* __restrict__ ei, const int* __restrict__ flag,
                          int* __restrict__ src, int* __restrict__ dst, int e) {
    int i = blockIdx.x * blockDim.x + threadIdx.x;
    if (i >= e) return;
    if (*flag) {
        const long long* p = (const long long*)ei;
        src[i] = (int)p[i];
        dst[i] = (int)p[e + i];
    } else {
        const int* p = (const int*)ei;
        src[i] = p[i];
        dst[i] = p[e + i];
    }
}

// ---------------------------------------------------------------------------
__global__ void k_zero_cnt(int* cnt, int n) {
    int i = blockIdx.x * blockDim.x + threadIdx.x;
    if (i < n) cnt[i] = 0;
}

__global__ void k_count(const int* __restrict__ dst, int* cnt, int e) {
    int i = blockIdx.x * blockDim.x + threadIdx.x;
    if (i < e) atomicAdd(&cnt[dst[i]], 1);
}

__global__ void k_dinv(const int* __restrict__ cnt, float* dinv, int n) {
    int i = blockIdx.x * blockDim.x + threadIdx.x;
    if (i < n) dinv[i] = rsqrtf((float)(cnt[i] + 1));   // +1 self-loop
}

// Single-block exclusive scan over n ints (n up to ~64K; 1024 threads).
__global__ void k_scan(const int* __restrict__ cnt, int* __restrict__ row_ptr, int n) {
    __shared__ int ws[32];
    __shared__ int carry;
    const int lane = threadIdx.x & 31, wid = threadIdx.x >> 5;
    if (threadIdx.x == 0) carry = 0;
    __syncthreads();
    for (int base = 0; base < n; base += 1024) {
        int i = base + threadIdx.x;
        int v = (i < n) ? cnt[i] : 0;
        int x = v;
        #pragma unroll
        for (int o = 1; o < 32; o <<= 1) {
            int y = __shfl_up_sync(0xffffffffu, x, o);
            if (lane >= o) x += y;
        }
        if (lane == 31) ws[wid] = x;
        __syncthreads();
        if (wid == 0) {
            int y = ws[lane];
            #pragma unroll
            for (int o = 1; o < 32; o <<= 1) {
                int z = __shfl_up_sync(0xffffffffu, y, o);
                if (lane >= o) y += z;
            }
            ws[lane] = y;
        }
        __syncthreads();
        int excl = carry + ((wid > 0) ? ws[wid - 1] : 0) + x - v;
        if (i < n) row_ptr[i] = excl;
        __syncthreads();
        if (threadIdx.x == 0) carry += ws[31];
        __syncthreads();
    }
    if (threadIdx.x == 0) row_ptr[n] = carry;
}

__global__ void k_copy(const int* __restrict__ a, int* __restrict__ b, int n) {
    int i = blockIdx.x * blockDim.x + threadIdx.x;
    if (i < n) b[i] = a[i];
}

__global__ void k_fill(const int* __restrict__ src, const int* __restrict__ dst,
                       int* cursor, int* __restrict__ adj, int e) {
    int i = blockIdx.x * blockDim.x + threadIdx.x;
    if (i >= e) return;
    int d = dst[i];
    int p = atomicAdd(&cursor[d], 1);
    adj[p] = src[i];
}

// ---------------------------------------------------------------------------
// C[m][0:128] = (sum_k A[m][k] * W[k][n]) * scale[m]
__global__ void __launch_bounds__(256, 1)
k_gemm128(const float4* __restrict__ A, const float* __restrict__ W,
          const float* __restrict__ scale, float4* __restrict__ C, int n)
{
    extern __shared__ float sm[];
    float* xs = sm;                 // [128][132]
    float* ws = sm + 128 * 132;     // [128][128]
    const int m0 = blockIdx.x * 128;
    const int t  = threadIdx.x;

    #pragma unroll
    for (int i = 0; i < 16; i++) {
        int idx = t + 256 * i;
        ((float4*)ws)[idx] = ((const float4*)W)[idx];
    }
    #pragma unroll
    for (int i = 0; i < 16; i++) {
        int idx = t + 256 * i;
        int m = idx >> 5, k4 = idx & 31;
        float4 v = make_float4(0.f, 0.f, 0.f, 0.f);
        if (m0 + m < n) v = A[(size_t)(m0 + m) * 32 + k4];
        *(float4*)(xs + m * 132 + k4 * 4) = v;
    }
    __syncthreads();

    const int tcol = t & 15, trow = t >> 4;
    float acc[8][8];
    #pragma unroll
    for (int r = 0; r < 8; r++)
        #pragma unroll
        for (int c = 0; c < 8; c++) acc[r][c] = 0.f;

    const float* xb = xs + trow * 8 * 132;
    #pragma unroll 8
    for (int k = 0; k < 128; k++) {
        float4 b0 = *(const float4*)(ws + k * 128 + tcol * 4);
        float4 b1 = *(const float4*)(ws + k * 128 + 64 + tcol * 4);
        float b[8] = {b0.x, b0.y, b0.z, b0.w, b1.x, b1.y, b1.z, b1.w};
        #pragma unroll
        for (int r = 0; r < 8; r++) {
            float a = xb[r * 132 + k];
            #pragma unroll
            for (int c = 0; c < 8; c++) acc[r][c] = fmaf(a, b[c], acc[r][c]);
        }
    }

    #pragma unroll
    for (int r = 0; r < 8; r++) {
        int m = m0 + trow * 8 + r;
        if (m < n) {
            float s = scale[m];
            C[(size_t)m * 32 + tcol]      = make_float4(acc[r][0]*s, acc[r][1]*s, acc[r][2]*s, acc[r][3]*s);
            C[(size_t)m * 32 + 16 + tcol] = make_float4(acc[r][4]*s, acc[r][5]*s, acc[r][6]*s, acc[r][7]*s);
        }
    }
}

// ---------------------------------------------------------------------------
// Fused aggregation: one warp per node.
// out[d] = act( (h[d] + sum_{s in adj[d]} h[s]) * dinv[d] + b )
__global__ void __launch_bounds__(256)
k_gather(const float4* __restrict__ h, const int* __restrict__ row_ptr,
         const int* __restrict__ adj, const float* __restrict__ dinv,
         const float* __restrict__ b, float4* __restrict__ out, int n, int relu)
{
    int w = (blockIdx.x * 256 + threadIdx.x) >> 5;
    int lane = threadIdx.x & 31;
    if (w >= n) return;
    int beg = __ldg(&row_ptr[w]);
    int end = __ldg(&row_ptr[w + 1]);

    float4 acc = h[(size_t)w * 32 + lane];   // self-loop term
    float4 acc2 = make_float4(0.f, 0.f, 0.f, 0.f);

    int i = beg;
    for (; i + 1 < end; i += 2) {
        int s0 = __ldg(&adj[i]);
        int s1 = __ldg(&adj[i + 1]);
        float4 v0 = h[(size_t)s0 * 32 + lane];
        float4 v1 = h[(size_t)s1 * 32 + lane];
        acc.x  += v0.x; acc.y  += v0.y; acc.z  += v0.z; acc.w  += v0.w;
        acc2.x += v1.x; acc2.y += v1.y; acc2.z += v1.z; acc2.w += v1.w;
    }
    if (i < end) {
        int s0 = __ldg(&adj[i]);
        float4 v0 = h[(size_t)s0 * 32 + lane];
        acc.x += v0.x; acc.y += v0.y; acc.z += v0.z; acc.w += v0.w;
    }
    acc.x += acc2.x; acc.y += acc2.y; acc.z += acc2.z; acc.w += acc2.w;

    float sc = dinv[w];
    const float* bp = b + lane * 4;
    float4 r;
    r.x = acc.x * sc + bp[0];
    r.y = acc.y * sc + bp[1];
    r.z = acc.z * sc + bp[2];
    r.w = acc.w * sc + bp[3];
    if (relu) {
        r.x = fmaxf(r.x, 0.f); r.y = fmaxf(r.y, 0.f);
        r.z = fmaxf(r.z, 0.f); r.w = fmaxf(r.w, 0.f);
    }
    out[(size_t)w * 32 + lane] = r;
}

// ---------------------------------------------------------------------------
// out = softmax(H @ Wa + ba) over K=100 cols (padded to 128 in smem)
__global__ void __launch_bounds__(256, 1)
k_final(const float4* __restrict__ H, const float* __restrict__ Wa,
        const float* __restrict__ ba, float* __restrict__ out, int n)
{
    extern __shared__ float sm[];
    float* hs  = sm;                  // [128][132]
    float* was = sm + 128 * 132;      // [128][128] zero-padded
    float* bas = was + 128 * 128;     // [128]
    const int m0 = blockIdx.x * 128;
    const int t  = threadIdx.x;

    #pragma unroll
    for (int i = 0; i < 64; i++) {
        int idx = t + 256 * i;
        int k = idx >> 7, c = idx & 127;
        was[idx] = (c < 100) ? Wa[k * 100 + c] : 0.f;
    }
    if (t < 128) bas[t] = (t < 100) ? ba[t] : -1e30f;
    #pragma unroll
    for (int i = 0; i < 16; i++) {
        int idx = t + 256 * i;
        int m = idx >> 5, k4 = idx & 31;
        float4 v = make_float4(0.f, 0.f, 0.f, 0.f);
        if (m0 + m < n) v = H[(size_t)(m0 + m) * 32 + k4];
        *(float4*)(hs + m * 132 + k4 * 4) = v;
    }
    __syncthreads();

    const int tcol = t & 15, trow = t >> 4;
    float acc[8][8];
    #pragma unroll
    for (int r = 0; r < 8; r++)
        #pragma unroll
        for (int c = 0; c < 8; c++) acc[r][c] = 0.f;

    const float* xb = hs + trow * 8 * 132;
    #pragma unroll 8
    for (int k = 0; k < 128; k++) {
        float4 b0 = *(const float4*)(was + k * 128 + tcol * 4);
        float4 b1 = *(const float4*)(was + k * 128 + 64 + tcol * 4);
        float b[8] = {b0.x, b0.y, b0.z, b0.w, b1.x, b1.y, b1.z, b1.w};
        #pragma unroll
        for (int r = 0; r < 8; r++) {
            float a = xb[r * 132 + k];
            #pragma unroll
            for (int c = 0; c < 8; c++) acc[r][c] = fmaf(a, b[c], acc[r][c]);
        }
    }

    float bv[8];
    #pragma unroll
    for (int c = 0; c < 4; c++) bv[c]     = bas[tcol * 4 + c];
    #pragma unroll
    for (int c = 0; c < 4; c++) bv[4 + c] = bas[64 + tcol * 4 + c];

    #pragma unroll
    for (int r = 0; r < 8; r++) {
        float v[8];
        #pragma unroll
        for (int c = 0; c < 8; c++) v[c] = acc[r][c] + bv[c];
        float mx = v[0];
        #pragma unroll
        for (int c = 1; c < 8; c++) mx = fmaxf(mx, v[c]);
        #pragma unroll
        for (int o = 8; o >= 1; o >>= 1)
            mx = fmaxf(mx, __shfl_xor_sync(0xffffffffu, mx, o));
        float sum = 0.f;
        #pragma unroll
        for (int c = 0; c < 8; c++) { v[c] = expf(v[c] - mx); sum += v[c]; }
        #pragma unroll
        for (int o = 8; o >= 1; o >>= 1)
            sum += __shfl_xor_sync(0xffffffffu, sum, o);
        float inv = 1.0f / sum;

        int m = m0 + trow * 8 + r;
        if (m < n) {
            *(float4*)(out + (size_t)m * 100 + tcol * 4) =
                make_float4(v[0]*inv, v[1]*inv, v[2]*inv, v[3]*inv);
            if (tcol < 9)
                *(float4*)(out + (size_t)m * 100 + 64 + tcol * 4) =
                    make_float4(v[4]*inv, v[5]*inv, v[6]*inv, v[7]*inv);
        }
    }
}

// ---------------------------------------------------------------------------
extern "C" void kernel_launch(void* const* d_in, const int* in_sizes, int n_in,
                              void* d_out, int out_size)
{
    int ix = 0, ie = 1, iW1 = 2, ib1 = 3, iW2 = 4, ib2 = 5, iWa = 6, iba = 7;
    {
        int jx=-1, je=-1, jW1=-1, jW2=-1, jb1=-1, jb2=-1, jWa=-1, jba=-1;
        for (int i = 0; i < n_in; i++) {
            int s = in_sizes[i];
            if      (s == 6400000) jx = i;
            else if (s == 3200000) je = i;
            else if (s == 16384)   { if (jW1 < 0) jW1 = i; else jW2 = i; }
            else if (s == 128)     { if (jb1 < 0) jb1 = i; else jb2 = i; }
            else if (s == 12800)   jWa = i;
            else if (s == 100)     jba = i;
        }
        if (jx>=0 && je>=0 && jW1>=0 && jW2>=0 && jb1>=0 && jb2>=0 && jWa>=0 && jba>=0) {
            ix=jx; ie=je; iW1=jW1; iW2=jW2; ib1=jb1; ib2=jb2; iWa=jWa; iba=jba;
        }
    }

    const float4* x   = (const float4*)d_in[ix];
    const void*   ei  = d_in[ie];
    const float*  W1  = (const float*)d_in[iW1];
    const float*  b1  = (const float*)d_in[ib1];
    const float*  W2  = (const float*)d_in[iW2];
    const float*  b2  = (const float*)d_in[ib2];
    const float*  Wa  = (const float*)d_in[iWa];
    const float*  ba  = (const float*)d_in[iba];
    float*        out = (float*)d_out;

    const int n = in_sizes[ix] / D;       // 50000
    const int e = in_sizes[ie] / 2;       // 1600000

    float4 *B0, *B2;
    float *dinv;
    int *cnt, *rowptr, *cursor, *srcI, *dstI, *adj, *is64;
    cudaGetSymbolAddress((void**)&B0, g_B0);
    cudaGetSymbolAddress((void**)&B2, g_B2);
    cudaGetSymbolAddress((void**)&dinv, g_dinv);
    cudaGetSymbolAddress((void**)&cnt, g_cnt);
    cudaGetSymbolAddress((void**)&rowptr, g_rowptr);
    cudaGetSymbolAddress((void**)&cursor, g_cursor);
    cudaGetSymbolAddress((void**)&srcI, g_src);
    cudaGetSymbolAddress((void**)&dstI, g_dst);
    cudaGetSymbolAddress((void**)&adj, g_adj);
    cudaGetSymbolAddress((void**)&is64, g_is64);

    const int SMEM_GEMM  = (128 * 132 + 128 * 128) * 4;
    const int SMEM_FINAL = (128 * 132 + 128 * 128 + 128) * 4;
    cudaFuncSetAttribute(k_gemm128, cudaFuncAttributeMaxDynamicSharedMemorySize, SMEM_GEMM);
    cudaFuncSetAttribute(k_final,  cudaFuncAttributeMaxDynamicSharedMemorySize, SMEM_FINAL);

    const int gemm_blocks = (n + 127) / 128;
    const int nb = (n + 255) / 256;
    const int eb = (e + 255) / 256;
    const int gb = (n * 32 + 255) / 256;   // warp-per-node gather

    // decode edge index (dtype-robust)
    k_detect<<<1, 256>>>((const unsigned int*)ei, is64);
    k_convert<<<eb, 256>>>(ei, is64, srcI, dstI, e);

    // CSR build: counts -> dinv, row_ptr (scan), cursor copy, binning fill
    k_zero_cnt<<<nb, 256>>>(cnt, n);
    k_count<<<eb, 256>>>(dstI, cnt, e);
    k_dinv<<<nb, 256>>>(cnt, dinv, n);
    k_scan<<<1, 1024>>>(cnt, rowptr, n);
    k_copy<<<nb, 256>>>(rowptr, cursor, n);
    k_fill<<<eb, 256>>>(srcI, dstI, cursor, adj, e);

    // layer 1: gemm (pre-scaled by dinv[row]) -> fused gather/post
    k_gemm128<<<gemm_blocks, 256, SMEM_GEMM>>>(x, W1, dinv, B0, n);
    k_gather<<<gb, 256>>>(B0, rowptr, adj, dinv, b1, B2, n, 1);

    // layer 2
    k_gemm128<<<gemm_blocks, 256, SMEM_GEMM>>>(B2, W2, dinv, B0, n);
    k_gather<<<gb, 256>>>(B0, rowptr, adj, dinv, b2, B2, n, 0);

    // head + softmax
    k_final<<<gemm_blocks, 256, SMEM_FINAL>>>(B2, Wa, ba, out, n);
}

// round 6
// speedup vs baseline: 3.4432x; 1.0574x over previous
#include <cuda_runtime.h>
#include <cuda_fp16.h>

// Problem constants
#define D 128
#define NMAX 50000
#define EMAX 1600000

// Scratch (16B/8B-aligned types for vector LDG/STG)
__device__ uint2  g_H[NMAX * 32];    // pre-scaled linear output, fp16 (4 halves per uint2)
__device__ float4 g_B2[NMAX * 32];   // layer activation, fp32
__device__ float  g_dinv[NMAX];
__device__ int    g_cnt[NMAX];
__device__ int    g_rowptr[NMAX + 1];
__device__ int    g_cursor[NMAX];
__device__ int    g_adj[EMAX];
__device__ int    g_is64;

// ---------------------------------------------------------------------------
// Detect edge_index dtype (int64 vs int32): odd 32-bit words of int64 indices
// < 50000 are all zero; for int32 they are random node ids.
__global__ void k_detect(const unsigned int* __restrict__ p, int* flag) {
    __shared__ unsigned int s;
    if (threadIdx.x == 0) s = 0u;
    __syncthreads();
    unsigned int v = p[threadIdx.x * 2 + 1];
    #pragma unroll
    for (int o = 16; o >= 1; o >>= 1) v |= __shfl_xor_sync(0xffffffffu, v, o);
    if ((threadIdx.x & 31) == 0) atomicOr(&s, v);
    __syncthreads();
    if (threadIdx.x == 0) *flag = (s == 0u) ? 1 : 0;
}

__global__ void k_zero_cnt(int* cnt, int n) {
    int i = blockIdx.x * blockDim.x + threadIdx.x;
    if (i < n) cnt[i] = 0;
}

// Count incoming edges; decode dst inline (no intermediate array).
__global__ void k_count(const void* __restrict__ ei, const int* __restrict__ flag,
                        int* cnt, int e) {
    int i = blockIdx.x * blockDim.x + threadIdx.x;
    if (i >= e) return;
    int d = *flag ? (int)((const long long*)ei)[e + i]
                  : ((const int*)ei)[e + i];
    atomicAdd(&cnt[d], 1);
}

// Fused exclusive scan (4 elems/thread) + cursor copy + dinv compute.
__global__ void k_scan(const int* __restrict__ cnt, int* __restrict__ row_ptr,
                       int* __restrict__ cursor, float* __restrict__ dinv, int n) {
    __shared__ int ws[32];
    __shared__ int carry;
    const int lane = threadIdx.x & 31, wid = threadIdx.x >> 5;
    if (threadIdx.x == 0) carry = 0;
    __syncthreads();
    for (int base = 0; base < n; base += 4096) {
        int i0 = base + threadIdx.x * 4;
        int v[4], s = 0;
        #pragma unroll
        for (int j = 0; j < 4; j++) {
            int i = i0 + j;
            v[j] = (i < n) ? cnt[i] : 0;
            s += v[j];
        }
        int x = s;
        #pragma unroll
        for (int o = 1; o < 32; o <<= 1) {
            int y = __shfl_up_sync(0xffffffffu, x, o);
            if (lane >= o) x += y;
        }
        if (lane == 31) ws[wid] = x;
        __syncthreads();
        if (wid == 0) {
            int y = ws[lane];
            #pragma unroll
            for (int o = 1; o < 32; o <<= 1) {
                int z = __shfl_up_sync(0xffffffffu, y, o);
                if (lane >= o) y += z;
            }
            ws[lane] = y;
        }
        __syncthreads();
        int run = carry + ((wid > 0) ? ws[wid - 1] : 0) + x - s;
        #pragma unroll
        for (int j = 0; j < 4; j++) {
            int i = i0 + j;
            if (i < n) {
                row_ptr[i] = run;
                cursor[i]  = run;
                dinv[i]    = rsqrtf((float)(v[j] + 1));   // +1 self-loop
                run += v[j];
            }
        }
        __syncthreads();
        if (threadIdx.x == 0) carry += ws[31];
        __syncthreads();
    }
    if (threadIdx.x == 0) row_ptr[n] = carry;
}

// Bin edges into CSR; decode src/dst inline.
__global__ void k_fill(const void* __restrict__ ei, const int* __restrict__ flag,
                       int* cursor, int* __restrict__ adj, int e) {
    int i = blockIdx.x * blockDim.x + threadIdx.x;
    if (i >= e) return;
    int s, d;
    if (*flag) {
        const long long* p = (const long long*)ei;
        s = (int)p[i]; d = (int)p[e + i];
    } else {
        const int* p = (const int*)ei;
        s = p[i]; d = p[e + i];
    }
    int pos = atomicAdd(&cursor[d], 1);
    adj[pos] = s;
}

// ---------------------------------------------------------------------------
// C[m][0:128] = half( (sum_k A[m][k] * W[k][c]) * scale[m] )
__global__ void __launch_bounds__(256, 1)
k_gemm128h(const float4* __restrict__ A, const float* __restrict__ W,
           const float* __restrict__ scale, uint2* __restrict__ C, int n)
{
    extern __shared__ float sm[];
    float* xs = sm;                 // [128][132]
    float* ws = sm + 128 * 132;     // [128][128]
    const int m0 = blockIdx.x * 128;
    const int t  = threadIdx.x;

    #pragma unroll
    for (int i = 0; i < 16; i++) {
        int idx = t + 256 * i;
        ((float4*)ws)[idx] = ((const float4*)W)[idx];
    }
    #pragma unroll
    for (int i = 0; i < 16; i++) {
        int idx = t + 256 * i;
        int m = idx >> 5, k4 = idx & 31;
        float4 v = make_float4(0.f, 0.f, 0.f, 0.f);
        if (m0 + m < n) v = A[(size_t)(m0 + m) * 32 + k4];
        *(float4*)(xs + m * 132 + k4 * 4) = v;
    }
    __syncthreads();

    const int tcol = t & 15, trow = t >> 4;
    float acc[8][8];
    #pragma unroll
    for (int r = 0; r < 8; r++)
        #pragma unroll
        for (int c = 0; c < 8; c++) acc[r][c] = 0.f;

    const float* xb = xs + trow * 8 * 132;
    #pragma unroll 8
    for (int k = 0; k < 128; k++) {
        float4 b0 = *(const float4*)(ws + k * 128 + tcol * 4);
        float4 b1 = *(const float4*)(ws + k * 128 + 64 + tcol * 4);
        float b[8] = {b0.x, b0.y, b0.z, b0.w, b1.x, b1.y, b1.z, b1.w};
        #pragma unroll
        for (int r = 0; r < 8; r++) {
            float a = xb[r * 132 + k];
            #pragma unroll
            for (int c = 0; c < 8; c++) acc[r][c] = fmaf(a, b[c], acc[r][c]);
        }
    }

    #pragma unroll
    for (int r = 0; r < 8; r++) {
        int m = m0 + trow * 8 + r;
        if (m < n) {
            float s = scale[m];
            __half2 p0 = __float22half2_rn(make_float2(acc[r][0]*s, acc[r][1]*s));
            __half2 p1 = __float22half2_rn(make_float2(acc[r][2]*s, acc[r][3]*s));
            __half2 p2 = __float22half2_rn(make_float2(acc[r][4]*s, acc[r][5]*s));
            __half2 p3 = __float22half2_rn(make_float2(acc[r][6]*s, acc[r][7]*s));
            uint2 o0 = make_uint2(*(unsigned*)&p0, *(unsigned*)&p1);
            uint2 o1 = make_uint2(*(unsigned*)&p2, *(unsigned*)&p3);
            C[(size_t)m * 32 + tcol]      = o0;
            C[(size_t)m * 32 + 16 + tcol] = o1;
        }
    }
}

// ---------------------------------------------------------------------------
__device__ __forceinline__ void acc_add(float4& a, uint2 v) {
    __half2 p0 = *(__half2*)&v.x;
    __half2 p1 = *(__half2*)&v.y;
    float2 f0 = __half22float2(p0);
    float2 f1 = __half22float2(p1);
    a.x += f0.x; a.y += f0.y; a.z += f1.x; a.w += f1.y;
}

// Fused aggregation: one warp per node.
// out[d] = act( (h[d] + sum_{s in adj[d]} h[s]) * dinv[d] + b )   (h in fp16)
__global__ void __launch_bounds__(256)
k_gather(const uint2* __restrict__ h, const int* __restrict__ row_ptr,
         const int* __restrict__ adj, const float* __restrict__ dinv,
         const float* __restrict__ b, float4* __restrict__ out, int n, int relu)
{
    int w = (blockIdx.x * 256 + threadIdx.x) >> 5;
    int lane = threadIdx.x & 31;
    if (w >= n) return;
    int beg = __ldg(&row_ptr[w]);
    int end = __ldg(&row_ptr[w + 1]);

    float4 acc  = make_float4(0.f, 0.f, 0.f, 0.f);
    float4 acc2 = make_float4(0.f, 0.f, 0.f, 0.f);
    acc_add(acc, h[(size_t)w * 32 + lane]);   // self-loop term

    int i = beg;
    for (; i + 3 < end; i += 4) {
        int s0 = __ldg(&adj[i]);
        int s1 = __ldg(&adj[i + 1]);
        int s2 = __ldg(&adj[i + 2]);
        int s3 = __ldg(&adj[i + 3]);
        uint2 v0 = h[(size_t)s0 * 32 + lane];
        uint2 v1 = h[(size_t)s1 * 32 + lane];
        uint2 v2 = h[(size_t)s2 * 32 + lane];
        uint2 v3 = h[(size_t)s3 * 32 + lane];
        acc_add(acc, v0);  acc_add(acc2, v1);
        acc_add(acc, v2);  acc_add(acc2, v3);
    }
    for (; i < end; i++) {
        int s0 = __ldg(&adj[i]);
        acc_add(acc, h[(size_t)s0 * 32 + lane]);
    }
    acc.x += acc2.x; acc.y += acc2.y; acc.z += acc2.z; acc.w += acc2.w;

    float sc = dinv[w];
    const float* bp = b + lane * 4;
    float4 r;
    r.x = acc.x * sc + bp[0];
    r.y = acc.y * sc + bp[1];
    r.z = acc.z * sc + bp[2];
    r.w = acc.w * sc + bp[3];
    if (relu) {
        r.x = fmaxf(r.x, 0.f); r.y = fmaxf(r.y, 0.f);
        r.z = fmaxf(r.z, 0.f); r.w = fmaxf(r.w, 0.f);
    }
    out[(size_t)w * 32 + lane] = r;
}

// ---------------------------------------------------------------------------
// out = softmax(H @ Wa + ba) over K=100 cols (padded to 128 in smem)
__global__ void __launch_bounds__(256, 1)
k_final(const float4* __restrict__ H, const float* __restrict__ Wa,
        const float* __restrict__ ba, float* __restrict__ out, int n)
{
    extern __shared__ float sm[];
    float* hs  = sm;                  // [128][132]
    float* was = sm + 128 * 132;      // [128][128] zero-padded
    float* bas = was + 128 * 128;     // [128]
    const int m0 = blockIdx.x * 128;
    const int t  = threadIdx.x;

    #pragma unroll
    for (int i = 0; i < 64; i++) {
        int idx = t + 256 * i;
        int k = idx >> 7, c = idx & 127;
        was[idx] = (c < 100) ? Wa[k * 100 + c] : 0.f;
    }
    if (t < 128) bas[t] = (t < 100) ? ba[t] : -1e30f;
    #pragma unroll
    for (int i = 0; i < 16; i++) {
        int idx = t + 256 * i;
        int m = idx >> 5, k4 = idx & 31;
        float4 v = make_float4(0.f, 0.f, 0.f, 0.f);
        if (m0 + m < n) v = H[(size_t)(m0 + m) * 32 + k4];
        *(float4*)(hs + m * 132 + k4 * 4) = v;
    }
    __syncthreads();

    const int tcol = t & 15, trow = t >> 4;
    float acc[8][8];
    #pragma unroll
    for (int r = 0; r < 8; r++)
        #pragma unroll
        for (int c = 0; c < 8; c++) acc[r][c] = 0.f;

    const float* xb = hs + trow * 8 * 132;
    #pragma unroll 8
    for (int k = 0; k < 128; k++) {
        float4 b0 = *(const float4*)(was + k * 128 + tcol * 4);
        float4 b1 = *(const float4*)(was + k * 128 + 64 + tcol * 4);
        float b[8] = {b0.x, b0.y, b0.z, b0.w, b1.x, b1.y, b1.z, b1.w};
        #pragma unroll
        for (int r = 0; r < 8; r++) {
            float a = xb[r * 132 + k];
            #pragma unroll
            for (int c = 0; c < 8; c++) acc[r][c] = fmaf(a, b[c], acc[r][c]);
        }
    }

    float bv[8];
    #pragma unroll
    for (int c = 0; c < 4; c++) bv[c]     = bas[tcol * 4 + c];
    #pragma unroll
    for (int c = 0; c < 4; c++) bv[4 + c] = bas[64 + tcol * 4 + c];

    #pragma unroll
    for (int r = 0; r < 8; r++) {
        float v[8];
        #pragma unroll
        for (int c = 0; c < 8; c++) v[c] = acc[r][c] + bv[c];
        float mx = v[0];
        #pragma unroll
        for (int c = 1; c < 8; c++) mx = fmaxf(mx, v[c]);
        #pragma unroll
        for (int o = 8; o >= 1; o >>= 1)
            mx = fmaxf(mx, __shfl_xor_sync(0xffffffffu, mx, o));
        float sum = 0.f;
        #pragma unroll
        for (int c = 0; c < 8; c++) { v[c] = expf(v[c] - mx); sum += v[c]; }
        #pragma unroll
        for (int o = 8; o >= 1; o >>= 1)
            sum += __shfl_xor_sync(0xffffffffu, sum, o);
        float inv = 1.0f / sum;

        int m = m0 + trow * 8 + r;
        if (m < n) {
            *(float4*)(out + (size_t)m * 100 + tcol * 4) =
                make_float4(v[0]*inv, v[1]*inv, v[2]*inv, v[3]*inv);
            if (tcol < 9)
                *(float4*)(out + (size_t)m * 100 + 64 + tcol * 4) =
                    make_float4(v[4]*inv, v[5]*inv, v[6]*inv, v[7]*inv);
        }
    }
}

// ---------------------------------------------------------------------------
extern "C" void kernel_launch(void* const* d_in, const int* in_sizes, int n_in,
                              void* d_out, int out_size)
{
    int ix = 0, ie = 1, iW1 = 2, ib1 = 3, iW2 = 4, ib2 = 5, iWa = 6, iba = 7;
    {
        int jx=-1, je=-1, jW1=-1, jW2=-1, jb1=-1, jb2=-1, jWa=-1, jba=-1;
        for (int i = 0; i < n_in; i++) {
            int s = in_sizes[i];
            if      (s == 6400000) jx = i;
            else if (s == 3200000) je = i;
            else if (s == 16384)   { if (jW1 < 0) jW1 = i; else jW2 = i; }
            else if (s == 128)     { if (jb1 < 0) jb1 = i; else jb2 = i; }
            else if (s == 12800)   jWa = i;
            else if (s == 100)     jba = i;
        }
        if (jx>=0 && je>=0 && jW1>=0 && jW2>=0 && jb1>=0 && jb2>=0 && jWa>=0 && jba>=0) {
            ix=jx; ie=je; iW1=jW1; iW2=jW2; ib1=jb1; ib2=jb2; iWa=jWa; iba=jba;
        }
    }

    const float4* x   = (const float4*)d_in[ix];
    const void*   ei  = d_in[ie];
    const float*  W1  = (const float*)d_in[iW1];
    const float*  b1  = (const float*)d_in[ib1];
    const float*  W2  = (const float*)d_in[iW2];
    const float*  b2  = (const float*)d_in[ib2];
    const float*  Wa  = (const float*)d_in[iWa];
    const float*  ba  = (const float*)d_in[iba];
    float*        out = (float*)d_out;

    const int n = in_sizes[ix] / D;       // 50000
    const int e = in_sizes[ie] / 2;       // 1600000

    uint2  *H;
    float4 *B2;
    float  *dinv;
    int *cnt, *rowptr, *cursor, *adj, *is64;
    cudaGetSymbolAddress((void**)&H, g_H);
    cudaGetSymbolAddress((void**)&B2, g_B2);
    cudaGetSymbolAddress((void**)&dinv, g_dinv);
    cudaGetSymbolAddress((void**)&cnt, g_cnt);
    cudaGetSymbolAddress((void**)&rowptr, g_rowptr);
    cudaGetSymbolAddress((void**)&cursor, g_cursor);
    cudaGetSymbolAddress((void**)&adj, g_adj);
    cudaGetSymbolAddress((void**)&is64, g_is64);

    const int SMEM_GEMM  = (128 * 132 + 128 * 128) * 4;
    const int SMEM_FINAL = (128 * 132 + 128 * 128 + 128) * 4;
    cudaFuncSetAttribute(k_gemm128h, cudaFuncAttributeMaxDynamicSharedMemorySize, SMEM_GEMM);
    cudaFuncSetAttribute(k_final,   cudaFuncAttributeMaxDynamicSharedMemorySize, SMEM_FINAL);

    const int gemm_blocks = (n + 127) / 128;
    const int nb = (n + 255) / 256;
    const int eb = (e + 255) / 256;
    const int gb = (n * 32 + 255) / 256;   // warp-per-node gather

    // CSR build (dtype-robust, no intermediate src/dst arrays)
    k_detect<<<1, 256>>>((const unsigned int*)ei, is64);
    k_zero_cnt<<<nb, 256>>>(cnt, n);
    k_count<<<eb, 256>>>(ei, is64, cnt, e);
    k_scan<<<1, 1024>>>(cnt, rowptr, cursor, dinv, n);
    k_fill<<<eb, 256>>>(ei, is64, cursor, adj, e);

    // layer 1: gemm (pre-scaled by dinv[row], fp16 out) -> fused gather/post
    k_gemm128h<<<gemm_blocks, 256, SMEM_GEMM>>>(x, W1, dinv, H, n);
    k_gather<<<gb, 256>>>(H, rowptr, adj, dinv, b1, B2, n, 1);

    // layer 2
    k_gemm128h<<<gemm_blocks, 256, SMEM_GEMM>>>(B2, W2, dinv, H, n);
    k_gather<<<gb, 256>>>(H, rowptr, adj, dinv, b2, B2, n, 0);

    // head + softmax
    k_final<<<gemm_blocks, 256, SMEM_FINAL>>>(B2, Wa, ba, out, n);
}

// round 7
// speedup vs baseline: 3.9945x; 1.1601x over previous
#include <cuda_runtime.h>
#include <cuda_fp16.h>

// Problem constants
#define D 128
#define NMAX 50000
#define EMAX 1600000
#define SCAN_TILE 1024          // elems per scan block (256 thr x 4)
#define MAX_PARTIALS 256

// Scratch (16B/8B-aligned types for vector LDG/STG)
__device__ uint2  g_H[NMAX * 32];    // pre-scaled linear output, fp16
__device__ float4 g_B2[NMAX * 32];   // layer activation, fp32
__device__ float  g_dinv[NMAX];
__device__ int    g_cnt[NMAX];
__device__ int    g_rowptr[NMAX + 1];
__device__ int    g_cursor[NMAX];
__device__ int    g_adj[EMAX];
__device__ int    g_partials[MAX_PARTIALS];
__device__ int    g_is64;

// ---------------------------------------------------------------------------
// Detect edge_index dtype (int64 vs int32): odd 32-bit words of int64 indices
// < 50000 are all zero; for int32 they are random node ids.
__global__ void k_detect(const unsigned int* __restrict__ p, int* flag) {
    __shared__ unsigned int s;
    if (threadIdx.x == 0) s = 0u;
    __syncthreads();
    unsigned int v = p[threadIdx.x * 2 + 1];
    #pragma unroll
    for (int o = 16; o >= 1; o >>= 1) v |= __shfl_xor_sync(0xffffffffu, v, o);
    if ((threadIdx.x & 31) == 0) atomicOr(&s, v);
    __syncthreads();
    if (threadIdx.x == 0) *flag = (s == 0u) ? 1 : 0;
}

__global__ void k_zero_cnt(int* cnt, int n) {
    int i = blockIdx.x * blockDim.x + threadIdx.x;
    if (i < n) cnt[i] = 0;
}

// Count incoming edges; decode dst inline.
__global__ void k_count(const void* __restrict__ ei, const int* __restrict__ flag,
                        int* cnt, int e) {
    int i = blockIdx.x * blockDim.x + threadIdx.x;
    if (i >= e) return;
    int d = *flag ? (int)((const long long*)ei)[e + i]
                  : ((const int*)ei)[e + i];
    atomicAdd(&cnt[d], 1);
}

// ---------------------------------------------------------------------------
// 3-phase parallel exclusive scan over cnt[n], fused with cursor/dinv writes.

// Phase 1: per-block tile sums.
__global__ void k_scan_partial(const int* __restrict__ cnt, int* __restrict__ partials, int n) {
    __shared__ int ws[8];
    const int lane = threadIdx.x & 31, wid = threadIdx.x >> 5;
    int i0 = blockIdx.x * SCAN_TILE + threadIdx.x * 4;
    int s = 0;
    #pragma unroll
    for (int j = 0; j < 4; j++) {
        int i = i0 + j;
        if (i < n) s += cnt[i];
    }
    #pragma unroll
    for (int o = 16; o >= 1; o >>= 1) s += __shfl_xor_sync(0xffffffffu, s, o);
    if (lane == 0) ws[wid] = s;
    __syncthreads();
    if (threadIdx.x == 0) {
        int t = 0;
        #pragma unroll
        for (int j = 0; j < 8; j++) t += ws[j];
        partials[blockIdx.x] = t;
    }
}

// Phase 2: exclusive scan of block partials (single block, <=256 partials).
__global__ void k_scan_offsets(int* __restrict__ partials, int* __restrict__ row_ptr,
                               int nblk, int n) {
    __shared__ int sh[MAX_PARTIALS];
    int t = threadIdx.x;
    int v = (t < nblk) ? partials[t] : 0;
    sh[t] = v;
    __syncthreads();
    // Hillis-Steele inclusive scan
    #pragma unroll
    for (int o = 1; o < MAX_PARTIALS; o <<= 1) {
        int y = (t >= o) ? sh[t - o] : 0;
        __syncthreads();
        sh[t] += y;
        __syncthreads();
    }
    if (t < nblk) partials[t] = sh[t] - v;         // exclusive
    if (t == nblk - 1) row_ptr[n] = sh[t];         // total edge count
}

// Phase 3: local scan + global offset; fused rowptr/cursor/dinv writes.
__global__ void k_scan_final(const int* __restrict__ cnt, const int* __restrict__ partials,
                             int* __restrict__ row_ptr, int* __restrict__ cursor,
                             float* __restrict__ dinv, int n) {
    __shared__ int ws[8];
    const int lane = threadIdx.x & 31, wid = threadIdx.x >> 5;
    int i0 = blockIdx.x * SCAN_TILE + threadIdx.x * 4;
    int v[4], s = 0;
    #pragma unroll
    for (int j = 0; j < 4; j++) {
        int i = i0 + j;
        v[j] = (i < n) ? cnt[i] : 0;
        s += v[j];
    }
    int x = s;
    #pragma unroll
    for (int o = 1; o < 32; o <<= 1) {
        int y = __shfl_up_sync(0xffffffffu, x, o);
        if (lane >= o) x += y;
    }
    if (lane == 31) ws[wid] = x;
    __syncthreads();
    int warp_off = 0;
    if (wid > 0) {
        #pragma unroll
        for (int j = 0; j < 7; j++) if (j < wid) warp_off += ws[j];
    }
    int run = partials[blockIdx.x] + warp_off + x - s;
    #pragma unroll
    for (int j = 0; j < 4; j++) {
        int i = i0 + j;
        if (i < n) {
            row_ptr[i] = run;
            cursor[i]  = run;
            dinv[i]    = rsqrtf((float)(v[j] + 1));   // +1 self-loop
            run += v[j];
        }
    }
}

// Bin edges into CSR; decode src/dst inline.
__global__ void k_fill(const void* __restrict__ ei, const int* __restrict__ flag,
                       int* cursor, int* __restrict__ adj, int e) {
    int i = blockIdx.x * blockDim.x + threadIdx.x;
    if (i >= e) return;
    int s, d;
    if (*flag) {
        const long long* p = (const long long*)ei;
        s = (int)p[i]; d = (int)p[e + i];
    } else {
        const int* p = (const int*)ei;
        s = p[i]; d = p[e + i];
    }
    int pos = atomicAdd(&cursor[d], 1);
    adj[pos] = s;
}

// ---------------------------------------------------------------------------
// C[m][0:128] = half( (sum_k A[m][k] * W[k][c]) * scale[m] )
__global__ void __launch_bounds__(256, 1)
k_gemm128h(const float4* __restrict__ A, const float* __restrict__ W,
           const float* __restrict__ scale, uint2* __restrict__ C, int n)
{
    extern __shared__ float sm[];
    float* xs = sm;                 // [128][132]
    float* ws = sm + 128 * 132;     // [128][128]
    const int m0 = blockIdx.x * 128;
    const int t  = threadIdx.x;

    #pragma unroll
    for (int i = 0; i < 16; i++) {
        int idx = t + 256 * i;
        ((float4*)ws)[idx] = ((const float4*)W)[idx];
    }
    #pragma unroll
    for (int i = 0; i < 16; i++) {
        int idx = t + 256 * i;
        int m = idx >> 5, k4 = idx & 31;
        float4 v = make_float4(0.f, 0.f, 0.f, 0.f);
        if (m0 + m < n) v = A[(size_t)(m0 + m) * 32 + k4];
        *(float4*)(xs + m * 132 + k4 * 4) = v;
    }
    __syncthreads();

    const int tcol = t & 15, trow = t >> 4;
    float acc[8][8];
    #pragma unroll
    for (int r = 0; r < 8; r++)
        #pragma unroll
        for (int c = 0; c < 8; c++) acc[r][c] = 0.f;

    const float* xb = xs + trow * 8 * 132;
    #pragma unroll 8
    for (int k = 0; k < 128; k++) {
        float4 b0 = *(const float4*)(ws + k * 128 + tcol * 4);
        float4 b1 = *(const float4*)(ws + k * 128 + 64 + tcol * 4);
        float b[8] = {b0.x, b0.y, b0.z, b0.w, b1.x, b1.y, b1.z, b1.w};
        #pragma unroll
        for (int r = 0; r < 8; r++) {
            float a = xb[r * 132 + k];
            #pragma unroll
            for (int c = 0; c < 8; c++) acc[r][c] = fmaf(a, b[c], acc[r][c]);
        }
    }

    #pragma unroll
    for (int r = 0; r < 8; r++) {
        int m = m0 + trow * 8 + r;
        if (m < n) {
            float s = scale[m];
            __half2 p0 = __float22half2_rn(make_float2(acc[r][0]*s, acc[r][1]*s));
            __half2 p1 = __float22half2_rn(make_float2(acc[r][2]*s, acc[r][3]*s));
            __half2 p2 = __float22half2_rn(make_float2(acc[r][4]*s, acc[r][5]*s));
            __half2 p3 = __float22half2_rn(make_float2(acc[r][6]*s, acc[r][7]*s));
            uint2 o0 = make_uint2(*(unsigned*)&p0, *(unsigned*)&p1);
            uint2 o1 = make_uint2(*(unsigned*)&p2, *(unsigned*)&p3);
            C[(size_t)m * 32 + tcol]      = o0;
            C[(size_t)m * 32 + 16 + tcol] = o1;
        }
    }
}

// ---------------------------------------------------------------------------
__device__ __forceinline__ void acc_add(float4& a, uint2 v) {
    __half2 p0 = *(__half2*)&v.x;
    __half2 p1 = *(__half2*)&v.y;
    float2 f0 = __half22float2(p0);
    float2 f1 = __half22float2(p1);
    a.x += f0.x; a.y += f0.y; a.z += f1.x; a.w += f1.y;
}

// Fused aggregation: one warp per node.
__global__ void __launch_bounds__(256)
k_gather(const uint2* __restrict__ h, const int* __restrict__ row_ptr,
         const int* __restrict__ adj, const float* __restrict__ dinv,
         const float* __restrict__ b, float4* __restrict__ out, int n, int relu)
{
    int w = (blockIdx.x * 256 + threadIdx.x) >> 5;
    int lane = threadIdx.x & 31;
    if (w >= n) return;
    int beg = __ldg(&row_ptr[w]);
    int end = __ldg(&row_ptr[w + 1]);

    float4 acc  = make_float4(0.f, 0.f, 0.f, 0.f);
    float4 acc2 = make_float4(0.f, 0.f, 0.f, 0.f);
    acc_add(acc, h[(size_t)w * 32 + lane]);   // self-loop term

    int i = beg;
    for (; i + 3 < end; i += 4) {
        int s0 = __ldg(&adj[i]);
        int s1 = __ldg(&adj[i + 1]);
        int s2 = __ldg(&adj[i + 2]);
        int s3 = __ldg(&adj[i + 3]);
        uint2 v0 = h[(size_t)s0 * 32 + lane];
        uint2 v1 = h[(size_t)s1 * 32 + lane];
        uint2 v2 = h[(size_t)s2 * 32 + lane];
        uint2 v3 = h[(size_t)s3 * 32 + lane];
        acc_add(acc, v0);  acc_add(acc2, v1);
        acc_add(acc, v2);  acc_add(acc2, v3);
    }
    for (; i < end; i++) {
        int s0 = __ldg(&adj[i]);
        acc_add(acc, h[(size_t)s0 * 32 + lane]);
    }
    acc.x += acc2.x; acc.y += acc2.y; acc.z += acc2.z; acc.w += acc2.w;

    float sc = dinv[w];
    const float* bp = b + lane * 4;
    float4 r;
    r.x = acc.x * sc + bp[0];
    r.y = acc.y * sc + bp[1];
    r.z = acc.z * sc + bp[2];
    r.w = acc.w * sc + bp[3];
    if (relu) {
        r.x = fmaxf(r.x, 0.f); r.y = fmaxf(r.y, 0.f);
        r.z = fmaxf(r.z, 0.f); r.w = fmaxf(r.w, 0.f);
    }
    out[(size_t)w * 32 + lane] = r;
}

// ---------------------------------------------------------------------------
// out = softmax(H @ Wa + ba) over K=100 cols (padded to 128 in smem)
__global__ void __launch_bounds__(256, 1)
k_final(const float4* __restrict__ H, const float* __restrict__ Wa,
        const float* __restrict__ ba, float* __restrict__ out, int n)
{
    extern __shared__ float sm[];
    float* hs  = sm;                  // [128][132]
    float* was = sm + 128 * 132;      // [128][128] zero-padded
    float* bas = was + 128 * 128;     // [128]
    const int m0 = blockIdx.x * 128;
    const int t  = threadIdx.x;

    #pragma unroll
    for (int i = 0; i < 64; i++) {
        int idx = t + 256 * i;
        int k = idx >> 7, c = idx & 127;
        was[idx] = (c < 100) ? Wa[k * 100 + c] : 0.f;
    }
    if (t < 128) bas[t] = (t < 100) ? ba[t] : -1e30f;
    #pragma unroll
    for (int i = 0; i < 16; i++) {
        int idx = t + 256 * i;
        int m = idx >> 5, k4 = idx & 31;
        float4 v = make_float4(0.f, 0.f, 0.f, 0.f);
        if (m0 + m < n) v = H[(size_t)(m0 + m) * 32 + k4];
        *(float4*)(hs + m * 132 + k4 * 4) = v;
    }
    __syncthreads();

    const int tcol = t & 15, trow = t >> 4;
    float acc[8][8];
    #pragma unroll
    for (int r = 0; r < 8; r++)
        #pragma unroll
        for (int c = 0; c < 8; c++) acc[r][c] = 0.f;

    const float* xb = hs + trow * 8 * 132;
    #pragma unroll 8
    for (int k = 0; k < 128; k++) {
        float4 b0 = *(const float4*)(was + k * 128 + tcol * 4);
        float4 b1 = *(const float4*)(was + k * 128 + 64 + tcol * 4);
        float b[8] = {b0.x, b0.y, b0.z, b0.w, b1.x, b1.y, b1.z, b1.w};
        #pragma unroll
        for (int r = 0; r < 8; r++) {
            float a = xb[r * 132 + k];
            #pragma unroll
            for (int c = 0; c < 8; c++) acc[r][c] = fmaf(a, b[c], acc[r][c]);
        }
    }

    float bv[8];
    #pragma unroll
    for (int c = 0; c < 4; c++) bv[c]     = bas[tcol * 4 + c];
    #pragma unroll
    for (int c = 0; c < 4; c++) bv[4 + c] = bas[64 + tcol * 4 + c];

    #pragma unroll
    for (int r = 0; r < 8; r++) {
        float v[8];
        #pragma unroll
        for (int c = 0; c < 8; c++) v[c] = acc[r][c] + bv[c];
        float mx = v[0];
        #pragma unroll
        for (int c = 1; c < 8; c++) mx = fmaxf(mx, v[c]);
        #pragma unroll
        for (int o = 8; o >= 1; o >>= 1)
            mx = fmaxf(mx, __shfl_xor_sync(0xffffffffu, mx, o));
        float sum = 0.f;
        #pragma unroll
        for (int c = 0; c < 8; c++) { v[c] = expf(v[c] - mx); sum += v[c]; }
        #pragma unroll
        for (int o = 8; o >= 1; o >>= 1)
            sum += __shfl_xor_sync(0xffffffffu, sum, o);
        float inv = 1.0f / sum;

        int m = m0 + trow * 8 + r;
        if (m < n) {
            *(float4*)(out + (size_t)m * 100 + tcol * 4) =
                make_float4(v[0]*inv, v[1]*inv, v[2]*inv, v[3]*inv);
            if (tcol < 9)
                *(float4*)(out + (size_t)m * 100 + 64 + tcol * 4) =
                    make_float4(v[4]*inv, v[5]*inv, v[6]*inv, v[7]*inv);
        }
    }
}

// ---------------------------------------------------------------------------
extern "C" void kernel_launch(void* const* d_in, const int* in_sizes, int n_in,
                              void* d_out, int out_size)
{
    int ix = 0, ie = 1, iW1 = 2, ib1 = 3, iW2 = 4, ib2 = 5, iWa = 6, iba = 7;
    {
        int jx=-1, je=-1, jW1=-1, jW2=-1, jb1=-1, jb2=-1, jWa=-1, jba=-1;
        for (int i = 0; i < n_in; i++) {
            int s = in_sizes[i];
            if      (s == 6400000) jx = i;
            else if (s == 3200000) je = i;
            else if (s == 16384)   { if (jW1 < 0) jW1 = i; else jW2 = i; }
            else if (s == 128)     { if (jb1 < 0) jb1 = i; else jb2 = i; }
            else if (s == 12800)   jWa = i;
            else if (s == 100)     jba = i;
        }
        if (jx>=0 && je>=0 && jW1>=0 && jW2>=0 && jb1>=0 && jb2>=0 && jWa>=0 && jba>=0) {
            ix=jx; ie=je; iW1=jW1; iW2=jW2; ib1=jb1; ib2=jb2; iWa=jWa; iba=jba;
        }
    }

    const float4* x   = (const float4*)d_in[ix];
    const void*   ei  = d_in[ie];
    const float*  W1  = (const float*)d_in[iW1];
    const float*  b1  = (const float*)d_in[ib1];
    const float*  W2  = (const float*)d_in[iW2];
    const float*  b2  = (const float*)d_in[ib2];
    const float*  Wa  = (const float*)d_in[iWa];
    const float*  ba  = (const float*)d_in[iba];
    float*        out = (float*)d_out;

    const int n = in_sizes[ix] / D;       // 50000
    const int e = in_sizes[ie] / 2;       // 1600000

    uint2  *H;
    float4 *B2;
    float  *dinv;
    int *cnt, *rowptr, *cursor, *adj, *partials, *is64;
    cudaGetSymbolAddress((void**)&H, g_H);
    cudaGetSymbolAddress((void**)&B2, g_B2);
    cudaGetSymbolAddress((void**)&dinv, g_dinv);
    cudaGetSymbolAddress((void**)&cnt, g_cnt);
    cudaGetSymbolAddress((void**)&rowptr, g_rowptr);
    cudaGetSymbolAddress((void**)&cursor, g_cursor);
    cudaGetSymbolAddress((void**)&adj, g_adj);
    cudaGetSymbolAddress((void**)&partials, g_partials);
    cudaGetSymbolAddress((void**)&is64, g_is64);

    const int SMEM_GEMM  = (128 * 132 + 128 * 128) * 4;
    const int SMEM_FINAL = (128 * 132 + 128 * 128 + 128) * 4;
    cudaFuncSetAttribute(k_gemm128h, cudaFuncAttributeMaxDynamicSharedMemorySize, SMEM_GEMM);
    cudaFuncSetAttribute(k_final,   cudaFuncAttributeMaxDynamicSharedMemorySize, SMEM_FINAL);

    const int gemm_blocks = (n + 127) / 128;
    const int nb = (n + 255) / 256;
    const int eb = (e + 255) / 256;
    const int gb = (n * 32 + 255) / 256;                 // warp-per-node gather
    const int scan_blocks = (n + SCAN_TILE - 1) / SCAN_TILE;   // 49 for n=50000

    // CSR build (dtype-robust)
    k_detect<<<1, 256>>>((const unsigned int*)ei, is64);
    k_zero_cnt<<<nb, 256>>>(cnt, n);
    k_count<<<eb, 256>>>(ei, is64, cnt, e);
    k_scan_partial<<<scan_blocks, 256>>>(cnt, partials, n);
    k_scan_offsets<<<1, MAX_PARTIALS>>>(partials, rowptr, scan_blocks, n);
    k_scan_final<<<scan_blocks, 256>>>(cnt, partials, rowptr, cursor, dinv, n);
    k_fill<<<eb, 256>>>(ei, is64, cursor, adj, e);

    // layer 1: gemm (pre-scaled by dinv[row], fp16 out) -> fused gather/post
    k_gemm128h<<<gemm_blocks, 256, SMEM_GEMM>>>(x, W1, dinv, H, n);
    k_gather<<<gb, 256>>>(H, rowptr, adj, dinv, b1, B2, n, 1);

    // layer 2
    k_gemm128h<<<gemm_blocks, 256, SMEM_GEMM>>>(B2, W2, dinv, H, n);
    k_gather<<<gb, 256>>>(H, rowptr, adj, dinv, b2, B2, n, 0);

    // head + softmax
    k_final<<<gemm_blocks, 256, SMEM_FINAL>>>(B2, Wa, ba, out, n);
}

// round 8
// speedup vs baseline: 4.9435x; 1.2376x over previous
#include <cuda_runtime.h>
#include <cuda_fp16.h>

// Problem constants
#define D 128
#define NMAX 50000
#define EMAX 1600000
#define SCAN_TILE 1024
#define MAX_PARTIALS 256

// Scratch
__device__ uint2  g_H[NMAX * 32];    // pre-scaled linear output, fp16
__device__ float4 g_B2[NMAX * 32];   // layer activation, fp32
__device__ float  g_dinv[NMAX];
__device__ int    g_cnt[NMAX];
__device__ int    g_rowptr[NMAX + 1];
__device__ int    g_cursor[NMAX];
__device__ int    g_adj[EMAX];
__device__ int    g_partials[MAX_PARTIALS];
__device__ int    g_is64;

// ---------------------------------------------------------------------------
__global__ void k_detect(const unsigned int* __restrict__ p, int* flag) {
    __shared__ unsigned int s;
    if (threadIdx.x == 0) s = 0u;
    __syncthreads();
    unsigned int v = p[threadIdx.x * 2 + 1];
    #pragma unroll
    for (int o = 16; o >= 1; o >>= 1) v |= __shfl_xor_sync(0xffffffffu, v, o);
    if ((threadIdx.x & 31) == 0) atomicOr(&s, v);
    __syncthreads();
    if (threadIdx.x == 0) *flag = (s == 0u) ? 1 : 0;
}

__global__ void k_zero_cnt(int* cnt, int n) {
    int i = blockIdx.x * blockDim.x + threadIdx.x;
    if (i < n) cnt[i] = 0;
}

__global__ void k_count(const void* __restrict__ ei, const int* __restrict__ flag,
                        int* cnt, int e) {
    int i = blockIdx.x * blockDim.x + threadIdx.x;
    if (i >= e) return;
    int d = *flag ? (int)((const long long*)ei)[e + i]
                  : ((const int*)ei)[e + i];
    atomicAdd(&cnt[d], 1);
}

// ---------------------------------------------------------------------------
__global__ void k_scan_partial(const int* __restrict__ cnt, int* __restrict__ partials, int n) {
    __shared__ int ws[8];
    const int lane = threadIdx.x & 31, wid = threadIdx.x >> 5;
    int i0 = blockIdx.x * SCAN_TILE + threadIdx.x * 4;
    int s = 0;
    #pragma unroll
    for (int j = 0; j < 4; j++) {
        int i = i0 + j;
        if (i < n) s += cnt[i];
    }
    #pragma unroll
    for (int o = 16; o >= 1; o >>= 1) s += __shfl_xor_sync(0xffffffffu, s, o);
    if (lane == 0) ws[wid] = s;
    __syncthreads();
    if (threadIdx.x == 0) {
        int t = 0;
        #pragma unroll
        for (int j = 0; j < 8; j++) t += ws[j];
        partials[blockIdx.x] = t;
    }
}

__global__ void k_scan_offsets(int* __restrict__ partials, int* __restrict__ row_ptr,
                               int nblk, int n) {
    __shared__ int sh[MAX_PARTIALS];
    int t = threadIdx.x;
    int v = (t < nblk) ? partials[t] : 0;
    sh[t] = v;
    __syncthreads();
    #pragma unroll
    for (int o = 1; o < MAX_PARTIALS; o <<= 1) {
        int y = (t >= o) ? sh[t - o] : 0;
        __syncthreads();
        sh[t] += y;
        __syncthreads();
    }
    if (t < nblk) partials[t] = sh[t] - v;
    if (t == nblk - 1) row_ptr[n] = sh[t];
}

__global__ void k_scan_final(const int* __restrict__ cnt, const int* __restrict__ partials,
                             int* __restrict__ row_ptr, int* __restrict__ cursor,
                             float* __restrict__ dinv, int n) {
    __shared__ int ws[8];
    const int lane = threadIdx.x & 31, wid = threadIdx.x >> 5;
    int i0 = blockIdx.x * SCAN_TILE + threadIdx.x * 4;
    int v[4], s = 0;
    #pragma unroll
    for (int j = 0; j < 4; j++) {
        int i = i0 + j;
        v[j] = (i < n) ? cnt[i] : 0;
        s += v[j];
    }
    int x = s;
    #pragma unroll
    for (int o = 1; o < 32; o <<= 1) {
        int y = __shfl_up_sync(0xffffffffu, x, o);
        if (lane >= o) x += y;
    }
    if (lane == 31) ws[wid] = x;
    __syncthreads();
    int warp_off = 0;
    if (wid > 0) {
        #pragma unroll
        for (int j = 0; j < 7; j++) if (j < wid) warp_off += ws[j];
    }
    int run = partials[blockIdx.x] + warp_off + x - s;
    #pragma unroll
    for (int j = 0; j < 4; j++) {
        int i = i0 + j;
        if (i < n) {
            row_ptr[i] = run;
            cursor[i]  = run;
            dinv[i]    = rsqrtf((float)(v[j] + 1));
            run += v[j];
        }
    }
}

__global__ void k_fill(const void* __restrict__ ei, const int* __restrict__ flag,
                       int* cursor, int* __restrict__ adj, int e) {
    int i = blockIdx.x * blockDim.x + threadIdx.x;
    if (i >= e) return;
    int s, d;
    if (*flag) {
        const long long* p = (const long long*)ei;
        s = (int)p[i]; d = (int)p[e + i];
    } else {
        const int* p = (const int*)ei;
        s = p[i]; d = p[e + i];
    }
    int pos = atomicAdd(&cursor[d], 1);
    adj[pos] = s;
}

// ---------------------------------------------------------------------------
// Tensor-core GEMM: C[m][0:128] = half( (A[m][:] @ W) * scale[m] ), fp16 HMMA.
// 256 threads = 8 warps; warp tile 32(m) x 64(n); mma.m16n8k16 fp32 acc.
// smem: A fp16 [128][128] + W^T fp16 [128][128], both XOR-swizzled (16B chunks).
__global__ void __launch_bounds__(256, 1)
k_gemm128t(const float4* __restrict__ A, const float* __restrict__ W,
           const float* __restrict__ scale, uint2* __restrict__ C, int n)
{
    extern __shared__ __half smh[];
    __half* as = smh;            // [128][128] A tile (rows m, cols k)
    __half* bt = smh + 16384;    // [128][128] W^T   (rows n, cols k)
    const int m0 = blockIdx.x * 128;
    const int t  = threadIdx.x;

    // Load A -> fp16 swizzled. chunk = 8 halves (16B); 2048 chunks.
    #pragma unroll
    for (int i = 0; i < 8; i++) {
        int id = t + 256 * i;
        int m = id >> 4, c = id & 15;
        float4 v0 = make_float4(0.f,0.f,0.f,0.f), v1 = v0;
        if (m0 + m < n) {
            v0 = A[(size_t)(m0 + m) * 32 + c * 2];
            v1 = A[(size_t)(m0 + m) * 32 + c * 2 + 1];
        }
        __half2 h0 = __float22half2_rn(make_float2(v0.x, v0.y));
        __half2 h1 = __float22half2_rn(make_float2(v0.z, v0.w));
        __half2 h2 = __float22half2_rn(make_float2(v1.x, v1.y));
        __half2 h3 = __float22half2_rn(make_float2(v1.z, v1.w));
        uint4 u = make_uint4(*(unsigned*)&h0, *(unsigned*)&h1,
                             *(unsigned*)&h2, *(unsigned*)&h3);
        *(uint4*)(as + m * 128 + ((c ^ (m & 7)) << 3)) = u;
    }
    // Load W[k][n] -> bt[n][k] fp16 swizzled (transpose).
    #pragma unroll
    for (int i = 0; i < 8; i++) {
        int id = t + 256 * i;
        int ck = id >> 7;          // k-chunk 0..15
        int nn = id & 127;         // n (fastest -> coalesced)
        float f[8];
        #pragma unroll
        for (int j = 0; j < 8; j++) f[j] = W[(ck * 8 + j) * 128 + nn];
        __half2 h0 = __float22half2_rn(make_float2(f[0], f[1]));
        __half2 h1 = __float22half2_rn(make_float2(f[2], f[3]));
        __half2 h2 = __float22half2_rn(make_float2(f[4], f[5]));
        __half2 h3 = __float22half2_rn(make_float2(f[6], f[7]));
        uint4 u = make_uint4(*(unsigned*)&h0, *(unsigned*)&h1,
                             *(unsigned*)&h2, *(unsigned*)&h3);
        *(uint4*)(bt + nn * 128 + ((ck ^ (nn & 7)) << 3)) = u;
    }
    __syncthreads();

    const int wid = t >> 5, lane = t & 31;
    const int wm = (wid >> 1) * 32;      // warp m base within tile
    const int wn = (wid & 1) * 64;       // warp n base within tile

    float acc[2][8][4];
    #pragma unroll
    for (int mt = 0; mt < 2; mt++)
        #pragma unroll
        for (int nt = 0; nt < 8; nt++)
            #pragma unroll
            for (int j = 0; j < 4; j++) acc[mt][nt][j] = 0.f;

    const unsigned as_base = (unsigned)__cvta_generic_to_shared(as);
    const unsigned bt_base = (unsigned)__cvta_generic_to_shared(bt);
    const int ra = lane & 15;            // A frag row within 16
    const int ka = lane >> 4;            // A frag k chunk sel
    const int rbn = ((lane >> 4) << 3) + (lane & 7);   // B frag n within 16
    const int kb  = (lane >> 3) & 1;                   // B frag k chunk sel

    #pragma unroll
    for (int ks = 0; ks < 8; ks++) {
        unsigned a[2][4];
        #pragma unroll
        for (int mt = 0; mt < 2; mt++) {
            int row = wm + mt * 16 + ra;
            int c = ks * 2 + ka;
            unsigned addr = as_base + ((row << 8) + ((c ^ (row & 7)) << 4));
            asm volatile("ldmatrix.sync.aligned.m8n8.x4.shared.b16 {%0,%1,%2,%3}, [%4];"
                : "=r"(a[mt][0]), "=r"(a[mt][1]), "=r"(a[mt][2]), "=r"(a[mt][3])
                : "r"(addr));
        }
        unsigned b[4][4];
        #pragma unroll
        for (int np = 0; np < 4; np++) {
            int rn = wn + np * 16 + rbn;
            int c = ks * 2 + kb;
            unsigned addr = bt_base + ((rn << 8) + ((c ^ (rn & 7)) << 4));
            asm volatile("ldmatrix.sync.aligned.m8n8.x4.shared.b16 {%0,%1,%2,%3}, [%4];"
                : "=r"(b[np][0]), "=r"(b[np][1]), "=r"(b[np][2]), "=r"(b[np][3])
                : "r"(addr));
        }
        #pragma unroll
        for (int mt = 0; mt < 2; mt++)
            #pragma unroll
            for (int nt = 0; nt < 8; nt++) {
                unsigned b0 = b[nt >> 1][(nt & 1) * 2];
                unsigned b1 = b[nt >> 1][(nt & 1) * 2 + 1];
                asm volatile(
                    "mma.sync.aligned.m16n8k16.row.col.f32.f16.f16.f32 "
                    "{%0,%1,%2,%3}, {%4,%5,%6,%7}, {%8,%9}, {%0,%1,%2,%3};"
                    : "+f"(acc[mt][nt][0]), "+f"(acc[mt][nt][1]),
                      "+f"(acc[mt][nt][2]), "+f"(acc[mt][nt][3])
                    : "r"(a[mt][0]), "r"(a[mt][1]), "r"(a[mt][2]), "r"(a[mt][3]),
                      "r"(b0), "r"(b1));
            }
    }

    // Epilogue: scale by dinv[row], convert fp16, store half2 (4B).
    __half2* C2 = (__half2*)C;
    #pragma unroll
    for (int mt = 0; mt < 2; mt++) {
        int row0 = m0 + wm + mt * 16 + (lane >> 2);
        int row1 = row0 + 8;
        float s0 = (row0 < n) ? scale[row0] : 0.f;
        float s1 = (row1 < n) ? scale[row1] : 0.f;
        #pragma unroll
        for (int nt = 0; nt < 8; nt++) {
            int cp = (wn + nt * 8) / 2 + (lane & 3);   // half2 col index
            if (row0 < n) {
                __half2 h = __float22half2_rn(
                    make_float2(acc[mt][nt][0] * s0, acc[mt][nt][1] * s0));
                C2[(size_t)row0 * 64 + cp] = h;
            }
            if (row1 < n) {
                __half2 h = __float22half2_rn(
                    make_float2(acc[mt][nt][2] * s1, acc[mt][nt][3] * s1));
                C2[(size_t)row1 * 64 + cp] = h;
            }
        }
    }
}

// ---------------------------------------------------------------------------
__device__ __forceinline__ void acc_add(float4& a, uint2 v) {
    __half2 p0 = *(__half2*)&v.x;
    __half2 p1 = *(__half2*)&v.y;
    float2 f0 = __half22float2(p0);
    float2 f1 = __half22float2(p1);
    a.x += f0.x; a.y += f0.y; a.z += f1.x; a.w += f1.y;
}

__global__ void __launch_bounds__(256)
k_gather(const uint2* __restrict__ h, const int* __restrict__ row_ptr,
         const int* __restrict__ adj, const float* __restrict__ dinv,
         const float* __restrict__ b, float4* __restrict__ out, int n, int relu)
{
    int w = (blockIdx.x * 256 + threadIdx.x) >> 5;
    int lane = threadIdx.x & 31;
    if (w >= n) return;
    int beg = __ldg(&row_ptr[w]);
    int end = __ldg(&row_ptr[w + 1]);

    float4 acc  = make_float4(0.f, 0.f, 0.f, 0.f);
    float4 acc2 = make_float4(0.f, 0.f, 0.f, 0.f);
    acc_add(acc, h[(size_t)w * 32 + lane]);

    int i = beg;
    for (; i + 3 < end; i += 4) {
        int s0 = __ldg(&adj[i]);
        int s1 = __ldg(&adj[i + 1]);
        int s2 = __ldg(&adj[i + 2]);
        int s3 = __ldg(&adj[i + 3]);
        uint2 v0 = h[(size_t)s0 * 32 + lane];
        uint2 v1 = h[(size_t)s1 * 32 + lane];
        uint2 v2 = h[(size_t)s2 * 32 + lane];
        uint2 v3 = h[(size_t)s3 * 32 + lane];
        acc_add(acc, v0);  acc_add(acc2, v1);
        acc_add(acc, v2);  acc_add(acc2, v3);
    }
    for (; i < end; i++) {
        int s0 = __ldg(&adj[i]);
        acc_add(acc, h[(size_t)s0 * 32 + lane]);
    }
    acc.x += acc2.x; acc.y += acc2.y; acc.z += acc2.z; acc.w += acc2.w;

    float sc = dinv[w];
    const float* bp = b + lane * 4;
    float4 r;
    r.x = acc.x * sc + bp[0];
    r.y = acc.y * sc + bp[1];
    r.z = acc.z * sc + bp[2];
    r.w = acc.w * sc + bp[3];
    if (relu) {
        r.x = fmaxf(r.x, 0.f); r.y = fmaxf(r.y, 0.f);
        r.z = fmaxf(r.z, 0.f); r.w = fmaxf(r.w, 0.f);
    }
    out[(size_t)w * 32 + lane] = r;
}

// ---------------------------------------------------------------------------
__global__ void __launch_bounds__(256, 1)
k_final(const float4* __restrict__ H, const float* __restrict__ Wa,
        const float* __restrict__ ba, float* __restrict__ out, int n)
{
    extern __shared__ float sm[];
    float* hs  = sm;
    float* was = sm + 128 * 132;
    float* bas = was + 128 * 128;
    const int m0 = blockIdx.x * 128;
    const int t  = threadIdx.x;

    #pragma unroll
    for (int i = 0; i < 64; i++) {
        int idx = t + 256 * i;
        int k = idx >> 7, c = idx & 127;
        was[idx] = (c < 100) ? Wa[k * 100 + c] : 0.f;
    }
    if (t < 128) bas[t] = (t < 100) ? ba[t] : -1e30f;
    #pragma unroll
    for (int i = 0; i < 16; i++) {
        int idx = t + 256 * i;
        int m = idx >> 5, k4 = idx & 31;
        float4 v = make_float4(0.f, 0.f, 0.f, 0.f);
        if (m0 + m < n) v = H[(size_t)(m0 + m) * 32 + k4];
        *(float4*)(hs + m * 132 + k4 * 4) = v;
    }
    __syncthreads();

    const int tcol = t & 15, trow = t >> 4;
    float acc[8][8];
    #pragma unroll
    for (int r = 0; r < 8; r++)
        #pragma unroll
        for (int c = 0; c < 8; c++) acc[r][c] = 0.f;

    const float* xb = hs + trow * 8 * 132;
    #pragma unroll 8
    for (int k = 0; k < 128; k++) {
        float4 b0 = *(const float4*)(was + k * 128 + tcol * 4);
        float4 b1 = *(const float4*)(was + k * 128 + 64 + tcol * 4);
        float b[8] = {b0.x, b0.y, b0.z, b0.w, b1.x, b1.y, b1.z, b1.w};
        #pragma unroll
        for (int r = 0; r < 8; r++) {
            float a = xb[r * 132 + k];
            #pragma unroll
            for (int c = 0; c < 8; c++) acc[r][c] = fmaf(a, b[c], acc[r][c]);
        }
    }

    float bv[8];
    #pragma unroll
    for (int c = 0; c < 4; c++) bv[c]     = bas[tcol * 4 + c];
    #pragma unroll
    for (int c = 0; c < 4; c++) bv[4 + c] = bas[64 + tcol * 4 + c];

    #pragma unroll
    for (int r = 0; r < 8; r++) {
        float v[8];
        #pragma unroll
        for (int c = 0; c < 8; c++) v[c] = acc[r][c] + bv[c];
        float mx = v[0];
        #pragma unroll
        for (int c = 1; c < 8; c++) mx = fmaxf(mx, v[c]);
        #pragma unroll
        for (int o = 8; o >= 1; o >>= 1)
            mx = fmaxf(mx, __shfl_xor_sync(0xffffffffu, mx, o));
        float sum = 0.f;
        #pragma unroll
        for (int c = 0; c < 8; c++) { v[c] = expf(v[c] - mx); sum += v[c]; }
        #pragma unroll
        for (int o = 8; o >= 1; o >>= 1)
            sum += __shfl_xor_sync(0xffffffffu, sum, o);
        float inv = 1.0f / sum;

        int m = m0 + trow * 8 + r;
        if (m < n) {
            *(float4*)(out + (size_t)m * 100 + tcol * 4) =
                make_float4(v[0]*inv, v[1]*inv, v[2]*inv, v[3]*inv);
            if (tcol < 9)
                *(float4*)(out + (size_t)m * 100 + 64 + tcol * 4) =
                    make_float4(v[4]*inv, v[5]*inv, v[6]*inv, v[7]*inv);
        }
    }
}

// ---------------------------------------------------------------------------
extern "C" void kernel_launch(void* const* d_in, const int* in_sizes, int n_in,
                              void* d_out, int out_size)
{
    int ix = 0, ie = 1, iW1 = 2, ib1 = 3, iW2 = 4, ib2 = 5, iWa = 6, iba = 7;
    {
        int jx=-1, je=-1, jW1=-1, jW2=-1, jb1=-1, jb2=-1, jWa=-1, jba=-1;
        for (int i = 0; i < n_in; i++) {
            int s = in_sizes[i];
            if      (s == 6400000) jx = i;
            else if (s == 3200000) je = i;
            else if (s == 16384)   { if (jW1 < 0) jW1 = i; else jW2 = i; }
            else if (s == 128)     { if (jb1 < 0) jb1 = i; else jb2 = i; }
            else if (s == 12800)   jWa = i;
            else if (s == 100)     jba = i;
        }
        if (jx>=0 && je>=0 && jW1>=0 && jW2>=0 && jb1>=0 && jb2>=0 && jWa>=0 && jba>=0) {
            ix=jx; ie=je; iW1=jW1; iW2=jW2; ib1=jb1; ib2=jb2; iWa=jWa; iba=jba;
        }
    }

    const float4* x   = (const float4*)d_in[ix];
    const void*   ei  = d_in[ie];
    const float*  W1  = (const float*)d_in[iW1];
    const float*  b1  = (const float*)d_in[ib1];
    const float*  W2  = (const float*)d_in[iW2];
    const float*  b2  = (const float*)d_in[ib2];
    const float*  Wa  = (const float*)d_in[iWa];
    const float*  ba  = (const float*)d_in[iba];
    float*        out = (float*)d_out;

    const int n = in_sizes[ix] / D;
    const int e = in_sizes[ie] / 2;

    uint2  *H;
    float4 *B2;
    float  *dinv;
    int *cnt, *rowptr, *cursor, *adj, *partials, *is64;
    cudaGetSymbolAddress((void**)&H, g_H);
    cudaGetSymbolAddress((void**)&B2, g_B2);
    cudaGetSymbolAddress((void**)&dinv, g_dinv);
    cudaGetSymbolAddress((void**)&cnt, g_cnt);
    cudaGetSymbolAddress((void**)&rowptr, g_rowptr);
    cudaGetSymbolAddress((void**)&cursor, g_cursor);
    cudaGetSymbolAddress((void**)&adj, g_adj);
    cudaGetSymbolAddress((void**)&partials, g_partials);
    cudaGetSymbolAddress((void**)&is64, g_is64);

    const int SMEM_TC    = 2 * 128 * 128 * 2;              // 64KB fp16 tiles
    const int SMEM_FINAL = (128 * 132 + 128 * 128 + 128) * 4;
    cudaFuncSetAttribute(k_gemm128t, cudaFuncAttributeMaxDynamicSharedMemorySize, SMEM_TC);
    cudaFuncSetAttribute(k_final,   cudaFuncAttributeMaxDynamicSharedMemorySize, SMEM_FINAL);

    const int gemm_blocks = (n + 127) / 128;
    const int nb = (n + 255) / 256;
    const int eb = (e + 255) / 256;
    const int gb = (n * 32 + 255) / 256;
    const int scan_blocks = (n + SCAN_TILE - 1) / SCAN_TILE;

    // CSR build (dtype-robust)
    k_detect<<<1, 256>>>((const unsigned int*)ei, is64);
    k_zero_cnt<<<nb, 256>>>(cnt, n);
    k_count<<<eb, 256>>>(ei, is64, cnt, e);
    k_scan_partial<<<scan_blocks, 256>>>(cnt, partials, n);
    k_scan_offsets<<<1, MAX_PARTIALS>>>(partials, rowptr, scan_blocks, n);
    k_scan_final<<<scan_blocks, 256>>>(cnt, partials, rowptr, cursor, dinv, n);
    k_fill<<<eb, 256>>>(ei, is64, cursor, adj, e);

    // layer 1: tensor-core gemm (pre-scaled, fp16 out) -> fused gather/post
    k_gemm128t<<<gemm_blocks, 256, SMEM_TC>>>(x, W1, dinv, H, n);
    k_gather<<<gb, 256>>>(H, rowptr, adj, dinv, b1, B2, n, 1);

    // layer 2
    k_gemm128t<<<gemm_blocks, 256, SMEM_TC>>>(B2, W2, dinv, H, n);
    k_gather<<<gb, 256>>>(H, rowptr, adj, dinv, b2, B2, n, 0);

    // head + softmax
    k_final<<<gemm_blocks, 256, SMEM_FINAL>>>(B2, Wa, ba, out, n);
}

// round 9
// speedup vs baseline: 6.1450x; 1.2430x over previous
#include <cuda_runtime.h>
#include <cuda_fp16.h>

// Problem constants
#define D 128
#define NMAX 50000
#define EMAX 1600000
#define SCAN_TILE 1024
#define MAX_PARTIALS 256

// Scratch
__device__ uint2  g_H[NMAX * 32];    // pre-scaled linear output, fp16
__device__ float4 g_B2[NMAX * 32];   // layer activation, fp32
__device__ float  g_dinv[NMAX];
__device__ int    g_cnt[NMAX];
__device__ int    g_rowptr[NMAX + 1];
__device__ int    g_cursor[NMAX];
__device__ int    g_adj[EMAX];
__device__ int    g_partials[MAX_PARTIALS];
__device__ int    g_is64;

// ---------------------------------------------------------------------------
__global__ void k_detect(const unsigned int* __restrict__ p, int* flag) {
    __shared__ unsigned int s;
    if (threadIdx.x == 0) s = 0u;
    __syncthreads();
    unsigned int v = p[threadIdx.x * 2 + 1];
    #pragma unroll
    for (int o = 16; o >= 1; o >>= 1) v |= __shfl_xor_sync(0xffffffffu, v, o);
    if ((threadIdx.x & 31) == 0) atomicOr(&s, v);
    __syncthreads();
    if (threadIdx.x == 0) *flag = (s == 0u) ? 1 : 0;
}

__global__ void k_zero_cnt(int* cnt, int n) {
    int i = blockIdx.x * blockDim.x + threadIdx.x;
    if (i < n) cnt[i] = 0;
}

__global__ void k_count(const void* __restrict__ ei, const int* __restrict__ flag,
                        int* cnt, int e) {
    int i = blockIdx.x * blockDim.x + threadIdx.x;
    if (i >= e) return;
    int d = *flag ? (int)((const long long*)ei)[e + i]
                  : ((const int*)ei)[e + i];
    atomicAdd(&cnt[d], 1);
}

// ---------------------------------------------------------------------------
__global__ void k_scan_partial(const int* __restrict__ cnt, int* __restrict__ partials, int n) {
    __shared__ int ws[8];
    const int lane = threadIdx.x & 31, wid = threadIdx.x >> 5;
    int i0 = blockIdx.x * SCAN_TILE + threadIdx.x * 4;
    int s = 0;
    #pragma unroll
    for (int j = 0; j < 4; j++) {
        int i = i0 + j;
        if (i < n) s += cnt[i];
    }
    #pragma unroll
    for (int o = 16; o >= 1; o >>= 1) s += __shfl_xor_sync(0xffffffffu, s, o);
    if (lane == 0) ws[wid] = s;
    __syncthreads();
    if (threadIdx.x == 0) {
        int t = 0;
        #pragma unroll
        for (int j = 0; j < 8; j++) t += ws[j];
        partials[blockIdx.x] = t;
    }
}

__global__ void k_scan_offsets(int* __restrict__ partials, int* __restrict__ row_ptr,
                               int nblk, int n) {
    __shared__ int sh[MAX_PARTIALS];
    int t = threadIdx.x;
    int v = (t < nblk) ? partials[t] : 0;
    sh[t] = v;
    __syncthreads();
    #pragma unroll
    for (int o = 1; o < MAX_PARTIALS; o <<= 1) {
        int y = (t >= o) ? sh[t - o] : 0;
        __syncthreads();
        sh[t] += y;
        __syncthreads();
    }
    if (t < nblk) partials[t] = sh[t] - v;
    if (t == nblk - 1) row_ptr[n] = sh[t];
}

__global__ void k_scan_final(const int* __restrict__ cnt, const int* __restrict__ partials,
                             int* __restrict__ row_ptr, int* __restrict__ cursor,
                             float* __restrict__ dinv, int n) {
    __shared__ int ws[8];
    const int lane = threadIdx.x & 31, wid = threadIdx.x >> 5;
    int i0 = blockIdx.x * SCAN_TILE + threadIdx.x * 4;
    int v[4], s = 0;
    #pragma unroll
    for (int j = 0; j < 4; j++) {
        int i = i0 + j;
        v[j] = (i < n) ? cnt[i] : 0;
        s += v[j];
    }
    int x = s;
    #pragma unroll
    for (int o = 1; o < 32; o <<= 1) {
        int y = __shfl_up_sync(0xffffffffu, x, o);
        if (lane >= o) x += y;
    }
    if (lane == 31) ws[wid] = x;
    __syncthreads();
    int warp_off = 0;
    if (wid > 0) {
        #pragma unroll
        for (int j = 0; j < 7; j++) if (j < wid) warp_off += ws[j];
    }
    int run = partials[blockIdx.x] + warp_off + x - s;
    #pragma unroll
    for (int j = 0; j < 4; j++) {
        int i = i0 + j;
        if (i < n) {
            row_ptr[i] = run;
            cursor[i]  = run;
            dinv[i]    = rsqrtf((float)(v[j] + 1));
            run += v[j];
        }
    }
}

__global__ void k_fill(const void* __restrict__ ei, const int* __restrict__ flag,
                       int* cursor, int* __restrict__ adj, int e) {
    int i = blockIdx.x * blockDim.x + threadIdx.x;
    if (i >= e) return;
    int s, d;
    if (*flag) {
        const long long* p = (const long long*)ei;
        s = (int)p[i]; d = (int)p[e + i];
    } else {
        const int* p = (const int*)ei;
        s = p[i]; d = p[e + i];
    }
    int pos = atomicAdd(&cursor[d], 1);
    adj[pos] = s;
}

// ---------------------------------------------------------------------------
// Tensor-core GEMM: C[m][0:128] = half( (A[m][:] @ W) * scale[m] ), fp16 HMMA.
__global__ void __launch_bounds__(256, 1)
k_gemm128t(const float4* __restrict__ A, const float* __restrict__ W,
           const float* __restrict__ scale, uint2* __restrict__ C, int n)
{
    extern __shared__ __half smh[];
    __half* as = smh;            // [128][128] A tile
    __half* bt = smh + 16384;    // [128][128] W^T
    const int m0 = blockIdx.x * 128;
    const int t  = threadIdx.x;

    #pragma unroll
    for (int i = 0; i < 8; i++) {
        int id = t + 256 * i;
        int m = id >> 4, c = id & 15;
        float4 v0 = make_float4(0.f,0.f,0.f,0.f), v1 = v0;
        if (m0 + m < n) {
            v0 = A[(size_t)(m0 + m) * 32 + c * 2];
            v1 = A[(size_t)(m0 + m) * 32 + c * 2 + 1];
        }
        __half2 h0 = __float22half2_rn(make_float2(v0.x, v0.y));
        __half2 h1 = __float22half2_rn(make_float2(v0.z, v0.w));
        __half2 h2 = __float22half2_rn(make_float2(v1.x, v1.y));
        __half2 h3 = __float22half2_rn(make_float2(v1.z, v1.w));
        uint4 u = make_uint4(*(unsigned*)&h0, *(unsigned*)&h1,
                             *(unsigned*)&h2, *(unsigned*)&h3);
        *(uint4*)(as + m * 128 + ((c ^ (m & 7)) << 3)) = u;
    }
    #pragma unroll
    for (int i = 0; i < 8; i++) {
        int id = t + 256 * i;
        int ck = id >> 7;
        int nn = id & 127;
        float f[8];
        #pragma unroll
        for (int j = 0; j < 8; j++) f[j] = W[(ck * 8 + j) * 128 + nn];
        __half2 h0 = __float22half2_rn(make_float2(f[0], f[1]));
        __half2 h1 = __float22half2_rn(make_float2(f[2], f[3]));
        __half2 h2 = __float22half2_rn(make_float2(f[4], f[5]));
        __half2 h3 = __float22half2_rn(make_float2(f[6], f[7]));
        uint4 u = make_uint4(*(unsigned*)&h0, *(unsigned*)&h1,
                             *(unsigned*)&h2, *(unsigned*)&h3);
        *(uint4*)(bt + nn * 128 + ((ck ^ (nn & 7)) << 3)) = u;
    }
    __syncthreads();

    const int wid = t >> 5, lane = t & 31;
    const int wm = (wid >> 1) * 32;
    const int wn = (wid & 1) * 64;

    float acc[2][8][4];
    #pragma unroll
    for (int mt = 0; mt < 2; mt++)
        #pragma unroll
        for (int nt = 0; nt < 8; nt++)
            #pragma unroll
            for (int j = 0; j < 4; j++) acc[mt][nt][j] = 0.f;

    const unsigned as_base = (unsigned)__cvta_generic_to_shared(as);
    const unsigned bt_base = (unsigned)__cvta_generic_to_shared(bt);
    const int ra = lane & 15;
    const int ka = lane >> 4;
    const int rbn = ((lane >> 4) << 3) + (lane & 7);
    const int kb  = (lane >> 3) & 1;

    #pragma unroll
    for (int ks = 0; ks < 8; ks++) {
        unsigned a[2][4];
        #pragma unroll
        for (int mt = 0; mt < 2; mt++) {
            int row = wm + mt * 16 + ra;
            int c = ks * 2 + ka;
            unsigned addr = as_base + ((row << 8) + ((c ^ (row & 7)) << 4));
            asm volatile("ldmatrix.sync.aligned.m8n8.x4.shared.b16 {%0,%1,%2,%3}, [%4];"
                : "=r"(a[mt][0]), "=r"(a[mt][1]), "=r"(a[mt][2]), "=r"(a[mt][3])
                : "r"(addr));
        }
        unsigned b[4][4];
        #pragma unroll
        for (int np = 0; np < 4; np++) {
            int rn = wn + np * 16 + rbn;
            int c = ks * 2 + kb;
            unsigned addr = bt_base + ((rn << 8) + ((c ^ (rn & 7)) << 4));
            asm volatile("ldmatrix.sync.aligned.m8n8.x4.shared.b16 {%0,%1,%2,%3}, [%4];"
                : "=r"(b[np][0]), "=r"(b[np][1]), "=r"(b[np][2]), "=r"(b[np][3])
                : "r"(addr));
        }
        #pragma unroll
        for (int mt = 0; mt < 2; mt++)
            #pragma unroll
            for (int nt = 0; nt < 8; nt++) {
                unsigned b0 = b[nt >> 1][(nt & 1) * 2];
                unsigned b1 = b[nt >> 1][(nt & 1) * 2 + 1];
                asm volatile(
                    "mma.sync.aligned.m16n8k16.row.col.f32.f16.f16.f32 "
                    "{%0,%1,%2,%3}, {%4,%5,%6,%7}, {%8,%9}, {%0,%1,%2,%3};"
                    : "+f"(acc[mt][nt][0]), "+f"(acc[mt][nt][1]),
                      "+f"(acc[mt][nt][2]), "+f"(acc[mt][nt][3])
                    : "r"(a[mt][0]), "r"(a[mt][1]), "r"(a[mt][2]), "r"(a[mt][3]),
                      "r"(b0), "r"(b1));
            }
    }

    __half2* C2 = (__half2*)C;
    #pragma unroll
    for (int mt = 0; mt < 2; mt++) {
        int row0 = m0 + wm + mt * 16 + (lane >> 2);
        int row1 = row0 + 8;
        float s0 = (row0 < n) ? scale[row0] : 0.f;
        float s1 = (row1 < n) ? scale[row1] : 0.f;
        #pragma unroll
        for (int nt = 0; nt < 8; nt++) {
            int cp = (wn + nt * 8) / 2 + (lane & 3);
            if (row0 < n) {
                __half2 h = __float22half2_rn(
                    make_float2(acc[mt][nt][0] * s0, acc[mt][nt][1] * s0));
                C2[(size_t)row0 * 64 + cp] = h;
            }
            if (row1 < n) {
                __half2 h = __float22half2_rn(
                    make_float2(acc[mt][nt][2] * s1, acc[mt][nt][3] * s1));
                C2[(size_t)row1 * 64 + cp] = h;
            }
        }
    }
}

// ---------------------------------------------------------------------------
__device__ __forceinline__ void acc_add(float4& a, uint2 v) {
    __half2 p0 = *(__half2*)&v.x;
    __half2 p1 = *(__half2*)&v.y;
    float2 f0 = __half22float2(p0);
    float2 f1 = __half22float2(p1);
    a.x += f0.x; a.y += f0.y; a.z += f1.x; a.w += f1.y;
}

__global__ void __launch_bounds__(256)
k_gather(const uint2* __restrict__ h, const int* __restrict__ row_ptr,
         const int* __restrict__ adj, const float* __restrict__ dinv,
         const float* __restrict__ b, float4* __restrict__ out, int n, int relu)
{
    int w = (blockIdx.x * 256 + threadIdx.x) >> 5;
    int lane = threadIdx.x & 31;
    if (w >= n) return;
    int beg = __ldg(&row_ptr[w]);
    int end = __ldg(&row_ptr[w + 1]);

    float4 acc  = make_float4(0.f, 0.f, 0.f, 0.f);
    float4 acc2 = make_float4(0.f, 0.f, 0.f, 0.f);
    acc_add(acc, h[(size_t)w * 32 + lane]);

    int i = beg;
    for (; i + 3 < end; i += 4) {
        int s0 = __ldg(&adj[i]);
        int s1 = __ldg(&adj[i + 1]);
        int s2 = __ldg(&adj[i + 2]);
        int s3 = __ldg(&adj[i + 3]);
        uint2 v0 = h[(size_t)s0 * 32 + lane];
        uint2 v1 = h[(size_t)s1 * 32 + lane];
        uint2 v2 = h[(size_t)s2 * 32 + lane];
        uint2 v3 = h[(size_t)s3 * 32 + lane];
        acc_add(acc, v0);  acc_add(acc2, v1);
        acc_add(acc, v2);  acc_add(acc2, v3);
    }
    for (; i < end; i++) {
        int s0 = __ldg(&adj[i]);
        acc_add(acc, h[(size_t)s0 * 32 + lane]);
    }
    acc.x += acc2.x; acc.y += acc2.y; acc.z += acc2.z; acc.w += acc2.w;

    float sc = dinv[w];
    const float* bp = b + lane * 4;
    float4 r;
    r.x = acc.x * sc + bp[0];
    r.y = acc.y * sc + bp[1];
    r.z = acc.z * sc + bp[2];
    r.w = acc.w * sc + bp[3];
    if (relu) {
        r.x = fmaxf(r.x, 0.f); r.y = fmaxf(r.y, 0.f);
        r.z = fmaxf(r.z, 0.f); r.w = fmaxf(r.w, 0.f);
    }
    out[(size_t)w * 32 + lane] = r;
}

// ---------------------------------------------------------------------------
// Tensor-core head: out = softmax(H @ Wa + ba). Warp tile 16(m) x 128(n);
// each warp owns whole rows -> softmax via 2 shfl_xor within a quad.
__global__ void __launch_bounds__(256, 1)
k_final_tc(const float4* __restrict__ H, const float* __restrict__ Wa,
           const float* __restrict__ ba, float* __restrict__ out, int n)
{
    extern __shared__ __half smh[];
    __half* hs = smh;            // [128][128] H tile fp16, swizzled
    __half* wt = smh + 16384;    // [128][128] Wa^T fp16 (zero-padded), swizzled
    float*  bas = (float*)(smh + 32768);   // [128] bias, padded with -1e30
    const int m0 = blockIdx.x * 128;
    const int t  = threadIdx.x;

    #pragma unroll
    for (int i = 0; i < 8; i++) {
        int id = t + 256 * i;
        int m = id >> 4, c = id & 15;
        float4 v0 = make_float4(0.f,0.f,0.f,0.f), v1 = v0;
        if (m0 + m < n) {
            v0 = H[(size_t)(m0 + m) * 32 + c * 2];
            v1 = H[(size_t)(m0 + m) * 32 + c * 2 + 1];
        }
        __half2 h0 = __float22half2_rn(make_float2(v0.x, v0.y));
        __half2 h1 = __float22half2_rn(make_float2(v0.z, v0.w));
        __half2 h2 = __float22half2_rn(make_float2(v1.x, v1.y));
        __half2 h3 = __float22half2_rn(make_float2(v1.z, v1.w));
        uint4 u = make_uint4(*(unsigned*)&h0, *(unsigned*)&h1,
                             *(unsigned*)&h2, *(unsigned*)&h3);
        *(uint4*)(hs + m * 128 + ((c ^ (m & 7)) << 3)) = u;
    }
    // Wa[k][0:100] -> wt[n][k], zero pad n in [100,128)
    #pragma unroll
    for (int i = 0; i < 8; i++) {
        int id = t + 256 * i;
        int ck = id >> 7;
        int nn = id & 127;
        float f[8];
        #pragma unroll
        for (int j = 0; j < 8; j++)
            f[j] = (nn < 100) ? Wa[(ck * 8 + j) * 100 + nn] : 0.f;
        __half2 h0 = __float22half2_rn(make_float2(f[0], f[1]));
        __half2 h1 = __float22half2_rn(make_float2(f[2], f[3]));
        __half2 h2 = __float22half2_rn(make_float2(f[4], f[5]));
        __half2 h3 = __float22half2_rn(make_float2(f[6], f[7]));
        uint4 u = make_uint4(*(unsigned*)&h0, *(unsigned*)&h1,
                             *(unsigned*)&h2, *(unsigned*)&h3);
        *(uint4*)(wt + nn * 128 + ((ck ^ (nn & 7)) << 3)) = u;
    }
    if (t < 128) bas[t] = (t < 100) ? ba[t] : -1e30f;
    __syncthreads();

    const int wid = t >> 5, lane = t & 31;
    const int wm = wid * 16;     // 8 warps x 16 rows = 128 rows

    float acc[16][4];
    #pragma unroll
    for (int nt = 0; nt < 16; nt++)
        #pragma unroll
        for (int j = 0; j < 4; j++) acc[nt][j] = 0.f;

    const unsigned hs_base = (unsigned)__cvta_generic_to_shared(hs);
    const unsigned wt_base = (unsigned)__cvta_generic_to_shared(wt);
    const int ra = lane & 15;
    const int ka = lane >> 4;
    const int rbn = ((lane >> 4) << 3) + (lane & 7);
    const int kb  = (lane >> 3) & 1;

    #pragma unroll
    for (int ks = 0; ks < 8; ks++) {
        unsigned a[4];
        {
            int row = wm + ra;
            int c = ks * 2 + ka;
            unsigned addr = hs_base + ((row << 8) + ((c ^ (row & 7)) << 4));
            asm volatile("ldmatrix.sync.aligned.m8n8.x4.shared.b16 {%0,%1,%2,%3}, [%4];"
                : "=r"(a[0]), "=r"(a[1]), "=r"(a[2]), "=r"(a[3]) : "r"(addr));
        }
        #pragma unroll
        for (int np = 0; np < 8; np++) {
            unsigned b[4];
            int rn = np * 16 + rbn;
            int c = ks * 2 + kb;
            unsigned addr = wt_base + ((rn << 8) + ((c ^ (rn & 7)) << 4));
            asm volatile("ldmatrix.sync.aligned.m8n8.x4.shared.b16 {%0,%1,%2,%3}, [%4];"
                : "=r"(b[0]), "=r"(b[1]), "=r"(b[2]), "=r"(b[3]) : "r"(addr));
            #pragma unroll
            for (int half = 0; half < 2; half++) {
                int nt = np * 2 + half;
                asm volatile(
                    "mma.sync.aligned.m16n8k16.row.col.f32.f16.f16.f32 "
                    "{%0,%1,%2,%3}, {%4,%5,%6,%7}, {%8,%9}, {%0,%1,%2,%3};"
                    : "+f"(acc[nt][0]), "+f"(acc[nt][1]),
                      "+f"(acc[nt][2]), "+f"(acc[nt][3])
                    : "r"(a[0]), "r"(a[1]), "r"(a[2]), "r"(a[3]),
                      "r"(b[half * 2]), "r"(b[half * 2 + 1]));
            }
        }
    }

    // Softmax epilogue. Thread holds rows r0=wm+(lane>>2), r1=r0+8;
    // cols c = nt*8 + (lane&3)*2 (+1). Quad (lanes sharing lane>>2) covers a row.
    float v0[32], v1[32];
    float mx0 = -1e30f, mx1 = -1e30f;
    #pragma unroll
    for (int nt = 0; nt < 16; nt++) {
        int c = nt * 8 + (lane & 3) * 2;
        float bb0 = bas[c], bb1 = bas[c + 1];
        v0[nt*2]   = acc[nt][0] + bb0;  v0[nt*2+1] = acc[nt][1] + bb1;
        v1[nt*2]   = acc[nt][2] + bb0;  v1[nt*2+1] = acc[nt][3] + bb1;
        mx0 = fmaxf(mx0, fmaxf(v0[nt*2], v0[nt*2+1]));
        mx1 = fmaxf(mx1, fmaxf(v1[nt*2], v1[nt*2+1]));
    }
    mx0 = fmaxf(mx0, __shfl_xor_sync(0xffffffffu, mx0, 1));
    mx0 = fmaxf(mx0, __shfl_xor_sync(0xffffffffu, mx0, 2));
    mx1 = fmaxf(mx1, __shfl_xor_sync(0xffffffffu, mx1, 1));
    mx1 = fmaxf(mx1, __shfl_xor_sync(0xffffffffu, mx1, 2));
    float sum0 = 0.f, sum1 = 0.f;
    #pragma unroll
    for (int j = 0; j < 32; j++) {
        v0[j] = expf(v0[j] - mx0); sum0 += v0[j];
        v1[j] = expf(v1[j] - mx1); sum1 += v1[j];
    }
    sum0 += __shfl_xor_sync(0xffffffffu, sum0, 1);
    sum0 += __shfl_xor_sync(0xffffffffu, sum0, 2);
    sum1 += __shfl_xor_sync(0xffffffffu, sum1, 1);
    sum1 += __shfl_xor_sync(0xffffffffu, sum1, 2);
    float inv0 = 1.0f / sum0, inv1 = 1.0f / sum1;

    int r0 = m0 + wm + (lane >> 2);
    int r1 = r0 + 8;
    #pragma unroll
    for (int nt = 0; nt < 16; nt++) {
        int c = nt * 8 + (lane & 3) * 2;
        if (c < 100) {
            if (r0 < n)
                *(float2*)(out + (size_t)r0 * 100 + c) =
                    make_float2(v0[nt*2] * inv0, v0[nt*2+1] * inv0);
            if (r1 < n)
                *(float2*)(out + (size_t)r1 * 100 + c) =
                    make_float2(v1[nt*2] * inv1, v1[nt*2+1] * inv1);
        }
    }
}

// ---------------------------------------------------------------------------
extern "C" void kernel_launch(void* const* d_in, const int* in_sizes, int n_in,
                              void* d_out, int out_size)
{
    int ix = 0, ie = 1, iW1 = 2, ib1 = 3, iW2 = 4, ib2 = 5, iWa = 6, iba = 7;
    {
        int jx=-1, je=-1, jW1=-1, jW2=-1, jb1=-1, jb2=-1, jWa=-1, jba=-1;
        for (int i = 0; i < n_in; i++) {
            int s = in_sizes[i];
            if      (s == 6400000) jx = i;
            else if (s == 3200000) je = i;
            else if (s == 16384)   { if (jW1 < 0) jW1 = i; else jW2 = i; }
            else if (s == 128)     { if (jb1 < 0) jb1 = i; else jb2 = i; }
            else if (s == 12800)   jWa = i;
            else if (s == 100)     jba = i;
        }
        if (jx>=0 && je>=0 && jW1>=0 && jW2>=0 && jb1>=0 && jb2>=0 && jWa>=0 && jba>=0) {
            ix=jx; ie=je; iW1=jW1; iW2=jW2; ib1=jb1; ib2=jb2; iWa=jWa; iba=jba;
        }
    }

    const float4* x   = (const float4*)d_in[ix];
    const void*   ei  = d_in[ie];
    const float*  W1  = (const float*)d_in[iW1];
    const float*  b1  = (const float*)d_in[ib1];
    const float*  W2  = (const float*)d_in[iW2];
    const float*  b2  = (const float*)d_in[ib2];
    const float*  Wa  = (const float*)d_in[iWa];
    const float*  ba  = (const float*)d_in[iba];
    float*        out = (float*)d_out;

    const int n = in_sizes[ix] / D;
    const int e = in_sizes[ie] / 2;

    uint2  *H;
    float4 *B2;
    float  *dinv;
    int *cnt, *rowptr, *cursor, *adj, *partials, *is64;
    cudaGetSymbolAddress((void**)&H, g_H);
    cudaGetSymbolAddress((void**)&B2, g_B2);
    cudaGetSymbolAddress((void**)&dinv, g_dinv);
    cudaGetSymbolAddress((void**)&cnt, g_cnt);
    cudaGetSymbolAddress((void**)&rowptr, g_rowptr);
    cudaGetSymbolAddress((void**)&cursor, g_cursor);
    cudaGetSymbolAddress((void**)&adj, g_adj);
    cudaGetSymbolAddress((void**)&partials, g_partials);
    cudaGetSymbolAddress((void**)&is64, g_is64);

    const int SMEM_TC    = 2 * 128 * 128 * 2;              // 64KB
    const int SMEM_FINAL = 2 * 128 * 128 * 2 + 128 * 4;    // 64KB + bias
    cudaFuncSetAttribute(k_gemm128t, cudaFuncAttributeMaxDynamicSharedMemorySize, SMEM_TC);
    cudaFuncSetAttribute(k_final_tc, cudaFuncAttributeMaxDynamicSharedMemorySize, SMEM_FINAL);

    const int gemm_blocks = (n + 127) / 128;
    const int nb = (n + 255) / 256;
    const int eb = (e + 255) / 256;
    const int gb = (n * 32 + 255) / 256;
    const int scan_blocks = (n + SCAN_TILE - 1) / SCAN_TILE;

    // CSR build (dtype-robust)
    k_detect<<<1, 256>>>((const unsigned int*)ei, is64);
    k_zero_cnt<<<nb, 256>>>(cnt, n);
    k_count<<<eb, 256>>>(ei, is64, cnt, e);
    k_scan_partial<<<scan_blocks, 256>>>(cnt, partials, n);
    k_scan_offsets<<<1, MAX_PARTIALS>>>(partials, rowptr, scan_blocks, n);
    k_scan_final<<<scan_blocks, 256>>>(cnt, partials, rowptr, cursor, dinv, n);
    k_fill<<<eb, 256>>>(ei, is64, cursor, adj, e);

    // layer 1
    k_gemm128t<<<gemm_blocks, 256, SMEM_TC>>>(x, W1, dinv, H, n);
    k_gather<<<gb, 256>>>(H, rowptr, adj, dinv, b1, B2, n, 1);

    // layer 2
    k_gemm128t<<<gemm_blocks, 256, SMEM_TC>>>(B2, W2, dinv, H, n);
    k_gather<<<gb, 256>>>(H, rowptr, adj, dinv, b2, B2, n, 0);

    // head + softmax (tensor core)
    k_final_tc<<<gemm_blocks, 256, SMEM_FINAL>>>(B2, Wa, ba, out, n);
}

// round 10
// speedup vs baseline: 6.4644x; 1.0520x over previous
#include <cuda_runtime.h>
#include <cuda_fp16.h>

// Problem constants
#define D 128
#define NMAX 50000
#define EMAX 1600000
#define SCAN_TILE 1024
#define MAX_PARTIALS 256

// Scratch
__device__ uint2  g_H[NMAX * 32];    // pre-scaled linear output, fp16
__device__ float4 g_B2[NMAX * 32];   // layer activation, fp32
__device__ float  g_dinv[NMAX];
__device__ int    g_cnt[NMAX];
__device__ int    g_rowptr[NMAX + 1];
__device__ int    g_cursor[NMAX];
__device__ int    g_adj[EMAX];
__device__ int    g_partials[MAX_PARTIALS];
__device__ int    g_is64;

// ---------------------------------------------------------------------------
__global__ void k_detect(const unsigned int* __restrict__ p, int* flag) {
    __shared__ unsigned int s;
    if (threadIdx.x == 0) s = 0u;
    __syncthreads();
    unsigned int v = p[threadIdx.x * 2 + 1];
    #pragma unroll
    for (int o = 16; o >= 1; o >>= 1) v |= __shfl_xor_sync(0xffffffffu, v, o);
    if ((threadIdx.x & 31) == 0) atomicOr(&s, v);
    __syncthreads();
    if (threadIdx.x == 0) *flag = (s == 0u) ? 1 : 0;
}

__global__ void k_zero_cnt(int* cnt, int n) {
    int i = blockIdx.x * blockDim.x + threadIdx.x;
    if (i < n) cnt[i] = 0;
}

// Count incoming edges, 4 edges/thread vectorized.
__global__ void k_count(const void* __restrict__ ei, const int* __restrict__ flag,
                        int* cnt, int e) {
    int i = (blockIdx.x * blockDim.x + threadIdx.x) * 4;
    if (i >= e) return;
    int e4 = e & ~3;
    if (*flag) {
        const long long* base = (const long long*)ei + e;
        if (i < e4 && (e & 1) == 0) {
            const longlong2* p = (const longlong2*)base;
            longlong2 a = p[i >> 1];
            longlong2 b = p[(i >> 1) + 1];
            atomicAdd(&cnt[(int)a.x], 1);
            atomicAdd(&cnt[(int)a.y], 1);
            atomicAdd(&cnt[(int)b.x], 1);
            atomicAdd(&cnt[(int)b.y], 1);
        } else {
            for (int j = i; j < e && j < i + 4; j++)
                atomicAdd(&cnt[(int)base[j]], 1);
        }
        if (i == 0) {
            for (int j = e4; j < e; j++) atomicAdd(&cnt[(int)base[j]], 1);
        }
    } else {
        const int* base = (const int*)ei + e;
        if (i < e4 && (e & 3) == 0) {
            int4 d = ((const int4*)base)[i >> 2];
            atomicAdd(&cnt[d.x], 1);
            atomicAdd(&cnt[d.y], 1);
            atomicAdd(&cnt[d.z], 1);
            atomicAdd(&cnt[d.w], 1);
        } else {
            for (int j = i; j < e && j < i + 4; j++)
                atomicAdd(&cnt[base[j]], 1);
        }
    }
}

// ---------------------------------------------------------------------------
__global__ void k_scan_partial(const int* __restrict__ cnt, int* __restrict__ partials, int n) {
    __shared__ int ws[8];
    const int lane = threadIdx.x & 31, wid = threadIdx.x >> 5;
    int i0 = blockIdx.x * SCAN_TILE + threadIdx.x * 4;
    int s = 0;
    #pragma unroll
    for (int j = 0; j < 4; j++) {
        int i = i0 + j;
        if (i < n) s += cnt[i];
    }
    #pragma unroll
    for (int o = 16; o >= 1; o >>= 1) s += __shfl_xor_sync(0xffffffffu, s, o);
    if (lane == 0) ws[wid] = s;
    __syncthreads();
    if (threadIdx.x == 0) {
        int t = 0;
        #pragma unroll
        for (int j = 0; j < 8; j++) t += ws[j];
        partials[blockIdx.x] = t;
    }
}

__global__ void k_scan_offsets(int* __restrict__ partials, int* __restrict__ row_ptr,
                               int nblk, int n) {
    __shared__ int sh[MAX_PARTIALS];
    int t = threadIdx.x;
    int v = (t < nblk) ? partials[t] : 0;
    sh[t] = v;
    __syncthreads();
    #pragma unroll
    for (int o = 1; o < MAX_PARTIALS; o <<= 1) {
        int y = (t >= o) ? sh[t - o] : 0;
        __syncthreads();
        sh[t] += y;
        __syncthreads();
    }
    if (t < nblk) partials[t] = sh[t] - v;
    if (t == nblk - 1) row_ptr[n] = sh[t];
}

__global__ void k_scan_final(const int* __restrict__ cnt, const int* __restrict__ partials,
                             int* __restrict__ row_ptr, int* __restrict__ cursor,
                             float* __restrict__ dinv, int n) {
    __shared__ int ws[8];
    const int lane = threadIdx.x & 31, wid = threadIdx.x >> 5;
    int i0 = blockIdx.x * SCAN_TILE + threadIdx.x * 4;
    int v[4], s = 0;
    #pragma unroll
    for (int j = 0; j < 4; j++) {
        int i = i0 + j;
        v[j] = (i < n) ? cnt[i] : 0;
        s += v[j];
    }
    int x = s;
    #pragma unroll
    for (int o = 1; o < 32; o <<= 1) {
        int y = __shfl_up_sync(0xffffffffu, x, o);
        if (lane >= o) x += y;
    }
    if (lane == 31) ws[wid] = x;
    __syncthreads();
    int warp_off = 0;
    if (wid > 0) {
        #pragma unroll
        for (int j = 0; j < 7; j++) if (j < wid) warp_off += ws[j];
    }
    int run = partials[blockIdx.x] + warp_off + x - s;
    #pragma unroll
    for (int j = 0; j < 4; j++) {
        int i = i0 + j;
        if (i < n) {
            row_ptr[i] = run;
            cursor[i]  = run;
            dinv[i]    = rsqrtf((float)(v[j] + 1));
            run += v[j];
        }
    }
}

// Bin edges into CSR, 4 edges/thread vectorized.
__global__ void k_fill(const void* __restrict__ ei, const int* __restrict__ flag,
                       int* cursor, int* __restrict__ adj, int e) {
    int i = (blockIdx.x * blockDim.x + threadIdx.x) * 4;
    if (i >= e) return;
    int e4 = e & ~3;
    int sv[4], dv[4], cnt4 = 0;
    if (*flag) {
        const long long* sb = (const long long*)ei;
        const long long* db = sb + e;
        if (i < e4 && (e & 1) == 0) {
            const longlong2* sp = (const longlong2*)sb;
            const longlong2* dp = (const longlong2*)db;
            longlong2 s0 = sp[i >> 1], s1 = sp[(i >> 1) + 1];
            longlong2 d0 = dp[i >> 1], d1 = dp[(i >> 1) + 1];
            sv[0]=(int)s0.x; sv[1]=(int)s0.y; sv[2]=(int)s1.x; sv[3]=(int)s1.y;
            dv[0]=(int)d0.x; dv[1]=(int)d0.y; dv[2]=(int)d1.x; dv[3]=(int)d1.y;
            cnt4 = 4;
        } else {
            for (int j = i; j < e && j < i + 4; j++) {
                sv[cnt4] = (int)sb[j]; dv[cnt4] = (int)db[j]; cnt4++;
            }
        }
        if (i == 0) {
            for (int j = e4; j < e; j++) {
                int pos = atomicAdd(&cursor[(int)db[j]], 1);
                adj[pos] = (int)sb[j];
            }
        }
    } else {
        const int* sb = (const int*)ei;
        const int* db = sb + e;
        if (i < e4 && (e & 3) == 0) {
            int4 s4 = ((const int4*)sb)[i >> 2];
            int4 d4 = ((const int4*)db)[i >> 2];
            sv[0]=s4.x; sv[1]=s4.y; sv[2]=s4.z; sv[3]=s4.w;
            dv[0]=d4.x; dv[1]=d4.y; dv[2]=d4.z; dv[3]=d4.w;
            cnt4 = 4;
        } else {
            for (int j = i; j < e && j < i + 4; j++) {
                sv[cnt4] = sb[j]; dv[cnt4] = db[j]; cnt4++;
            }
        }
    }
    #pragma unroll
    for (int j = 0; j < 4; j++) {
        if (j < cnt4) {
            int pos = atomicAdd(&cursor[dv[j]], 1);
            adj[pos] = sv[j];
        }
    }
}

// ---------------------------------------------------------------------------
// Tensor-core GEMM: C[m][0:128] = half( (A[m][:] @ W) * scale[m] ), fp16 HMMA.
__global__ void __launch_bounds__(256, 1)
k_gemm128t(const float4* __restrict__ A, const float* __restrict__ W,
           const float* __restrict__ scale, uint2* __restrict__ C, int n)
{
    extern __shared__ __half smh[];
    __half* as = smh;
    __half* bt = smh + 16384;
    const int m0 = blockIdx.x * 128;
    const int t  = threadIdx.x;

    #pragma unroll
    for (int i = 0; i < 8; i++) {
        int id = t + 256 * i;
        int m = id >> 4, c = id & 15;
        float4 v0 = make_float4(0.f,0.f,0.f,0.f), v1 = v0;
        if (m0 + m < n) {
            v0 = A[(size_t)(m0 + m) * 32 + c * 2];
            v1 = A[(size_t)(m0 + m) * 32 + c * 2 + 1];
        }
        __half2 h0 = __float22half2_rn(make_float2(v0.x, v0.y));
        __half2 h1 = __float22half2_rn(make_float2(v0.z, v0.w));
        __half2 h2 = __float22half2_rn(make_float2(v1.x, v1.y));
        __half2 h3 = __float22half2_rn(make_float2(v1.z, v1.w));
        uint4 u = make_uint4(*(unsigned*)&h0, *(unsigned*)&h1,
                             *(unsigned*)&h2, *(unsigned*)&h3);
        *(uint4*)(as + m * 128 + ((c ^ (m & 7)) << 3)) = u;
    }
    #pragma unroll
    for (int i = 0; i < 8; i++) {
        int id = t + 256 * i;
        int ck = id >> 7;
        int nn = id & 127;
        float f[8];
        #pragma unroll
        for (int j = 0; j < 8; j++) f[j] = W[(ck * 8 + j) * 128 + nn];
        __half2 h0 = __float22half2_rn(make_float2(f[0], f[1]));
        __half2 h1 = __float22half2_rn(make_float2(f[2], f[3]));
        __half2 h2 = __float22half2_rn(make_float2(f[4], f[5]));
        __half2 h3 = __float22half2_rn(make_float2(f[6], f[7]));
        uint4 u = make_uint4(*(unsigned*)&h0, *(unsigned*)&h1,
                             *(unsigned*)&h2, *(unsigned*)&h3);
        *(uint4*)(bt + nn * 128 + ((ck ^ (nn & 7)) << 3)) = u;
    }
    __syncthreads();

    const int wid = t >> 5, lane = t & 31;
    const int wm = (wid >> 1) * 32;
    const int wn = (wid & 1) * 64;

    float acc[2][8][4];
    #pragma unroll
    for (int mt = 0; mt < 2; mt++)
        #pragma unroll
        for (int nt = 0; nt < 8; nt++)
            #pragma unroll
            for (int j = 0; j < 4; j++) acc[mt][nt][j] = 0.f;

    const unsigned as_base = (unsigned)__cvta_generic_to_shared(as);
    const unsigned bt_base = (unsigned)__cvta_generic_to_shared(bt);
    const int ra = lane & 15;
    const int ka = lane >> 4;
    const int rbn = ((lane >> 4) << 3) + (lane & 7);
    const int kb  = (lane >> 3) & 1;

    #pragma unroll
    for (int ks = 0; ks < 8; ks++) {
        unsigned a[2][4];
        #pragma unroll
        for (int mt = 0; mt < 2; mt++) {
            int row = wm + mt * 16 + ra;
            int c = ks * 2 + ka;
            unsigned addr = as_base + ((row << 8) + ((c ^ (row & 7)) << 4));
            asm volatile("ldmatrix.sync.aligned.m8n8.x4.shared.b16 {%0,%1,%2,%3}, [%4];"
                : "=r"(a[mt][0]), "=r"(a[mt][1]), "=r"(a[mt][2]), "=r"(a[mt][3])
                : "r"(addr));
        }
        unsigned b[4][4];
        #pragma unroll
        for (int np = 0; np < 4; np++) {
            int rn = wn + np * 16 + rbn;
            int c = ks * 2 + kb;
            unsigned addr = bt_base + ((rn << 8) + ((c ^ (rn & 7)) << 4));
            asm volatile("ldmatrix.sync.aligned.m8n8.x4.shared.b16 {%0,%1,%2,%3}, [%4];"
                : "=r"(b[np][0]), "=r"(b[np][1]), "=r"(b[np][2]), "=r"(b[np][3])
                : "r"(addr));
        }
        #pragma unroll
        for (int mt = 0; mt < 2; mt++)
            #pragma unroll
            for (int nt = 0; nt < 8; nt++) {
                unsigned b0 = b[nt >> 1][(nt & 1) * 2];
                unsigned b1 = b[nt >> 1][(nt & 1) * 2 + 1];
                asm volatile(
                    "mma.sync.aligned.m16n8k16.row.col.f32.f16.f16.f32 "
                    "{%0,%1,%2,%3}, {%4,%5,%6,%7}, {%8,%9}, {%0,%1,%2,%3};"
                    : "+f"(acc[mt][nt][0]), "+f"(acc[mt][nt][1]),
                      "+f"(acc[mt][nt][2]), "+f"(acc[mt][nt][3])
                    : "r"(a[mt][0]), "r"(a[mt][1]), "r"(a[mt][2]), "r"(a[mt][3]),
                      "r"(b0), "r"(b1));
            }
    }

    __half2* C2 = (__half2*)C;
    #pragma unroll
    for (int mt = 0; mt < 2; mt++) {
        int row0 = m0 + wm + mt * 16 + (lane >> 2);
        int row1 = row0 + 8;
        float s0 = (row0 < n) ? scale[row0] : 0.f;
        float s1 = (row1 < n) ? scale[row1] : 0.f;
        #pragma unroll
        for (int nt = 0; nt < 8; nt++) {
            int cp = (wn + nt * 8) / 2 + (lane & 3);
            if (row0 < n) {
                __half2 h = __float22half2_rn(
                    make_float2(acc[mt][nt][0] * s0, acc[mt][nt][1] * s0));
                C2[(size_t)row0 * 64 + cp] = h;
            }
            if (row1 < n) {
                __half2 h = __float22half2_rn(
                    make_float2(acc[mt][nt][2] * s1, acc[mt][nt][3] * s1));
                C2[(size_t)row1 * 64 + cp] = h;
            }
        }
    }
}

// ---------------------------------------------------------------------------
// Accumulate 8 halves (one uint4) into two float4 accumulators.
__device__ __forceinline__ void acc_add8(float4& a, float4& b, uint4 v) {
    float2 f0 = __half22float2(*(__half2*)&v.x);
    float2 f1 = __half22float2(*(__half2*)&v.y);
    float2 f2 = __half22float2(*(__half2*)&v.z);
    float2 f3 = __half22float2(*(__half2*)&v.w);
    a.x += f0.x; a.y += f0.y; a.z += f1.x; a.w += f1.y;
    b.x += f2.x; b.y += f2.y; b.z += f3.x; b.w += f3.y;
}

// Fused aggregation: one warp per node; half-warps split even/odd edges,
// each lane loads a 16B (uint4) chunk; butterfly-combine at the end.
__global__ void __launch_bounds__(256)
k_gather(const uint4* __restrict__ h4, const int* __restrict__ row_ptr,
         const int* __restrict__ adj, const float* __restrict__ dinv,
         const float* __restrict__ b, float4* __restrict__ out, int n, int relu)
{
    int w = (blockIdx.x * 256 + threadIdx.x) >> 5;
    int lane = threadIdx.x & 31;
    if (w >= n) return;
    const int half = lane >> 4, cl = lane & 15;
    int beg = __ldg(&row_ptr[w]);
    int end = __ldg(&row_ptr[w + 1]);

    float4 accA = make_float4(0.f,0.f,0.f,0.f);
    float4 accB = make_float4(0.f,0.f,0.f,0.f);
    if (half == 0) acc_add8(accA, accB, h4[(size_t)w * 16 + cl]);   // self-loop

    int i = beg + half;
    for (; i + 2 < end; i += 4) {
        int s0 = __ldg(&adj[i]);
        int s1 = __ldg(&adj[i + 2]);
        uint4 v0 = h4[(size_t)s0 * 16 + cl];
        uint4 v1 = h4[(size_t)s1 * 16 + cl];
        acc_add8(accA, accB, v0);
        acc_add8(accA, accB, v1);
    }
    for (; i < end; i += 2) {
        int s0 = __ldg(&adj[i]);
        acc_add8(accA, accB, h4[(size_t)s0 * 16 + cl]);
    }

    // Combine halves (same cl in lane and lane^16).
    accA.x += __shfl_xor_sync(0xffffffffu, accA.x, 16);
    accA.y += __shfl_xor_sync(0xffffffffu, accA.y, 16);
    accA.z += __shfl_xor_sync(0xffffffffu, accA.z, 16);
    accA.w += __shfl_xor_sync(0xffffffffu, accA.w, 16);
    accB.x += __shfl_xor_sync(0xffffffffu, accB.x, 16);
    accB.y += __shfl_xor_sync(0xffffffffu, accB.y, 16);
    accB.z += __shfl_xor_sync(0xffffffffu, accB.z, 16);
    accB.w += __shfl_xor_sync(0xffffffffu, accB.w, 16);

    float sc = dinv[w];
    float4 acc = (half == 0) ? accA : accB;
    float4 bb = ((const float4*)b)[cl * 2 + half];
    float4 r;
    r.x = acc.x * sc + bb.x;
    r.y = acc.y * sc + bb.y;
    r.z = acc.z * sc + bb.z;
    r.w = acc.w * sc + bb.w;
    if (relu) {
        r.x = fmaxf(r.x, 0.f); r.y = fmaxf(r.y, 0.f);
        r.z = fmaxf(r.z, 0.f); r.w = fmaxf(r.w, 0.f);
    }
    out[(size_t)w * 32 + cl * 2 + half] = r;
}

// ---------------------------------------------------------------------------
// Tensor-core head: out = softmax(H @ Wa + ba).
__global__ void __launch_bounds__(256, 1)
k_final_tc(const float4* __restrict__ H, const float* __restrict__ Wa,
           const float* __restrict__ ba, float* __restrict__ out, int n)
{
    extern __shared__ __half smh[];
    __half* hs = smh;
    __half* wt = smh + 16384;
    float*  bas = (float*)(smh + 32768);
    const int m0 = blockIdx.x * 128;
    const int t  = threadIdx.x;

    #pragma unroll
    for (int i = 0; i < 8; i++) {
        int id = t + 256 * i;
        int m = id >> 4, c = id & 15;
        float4 v0 = make_float4(0.f,0.f,0.f,0.f), v1 = v0;
        if (m0 + m < n) {
            v0 = H[(size_t)(m0 + m) * 32 + c * 2];
            v1 = H[(size_t)(m0 + m) * 32 + c * 2 + 1];
        }
        __half2 h0 = __float22half2_rn(make_float2(v0.x, v0.y));
        __half2 h1 = __float22half2_rn(make_float2(v0.z, v0.w));
        __half2 h2 = __float22half2_rn(make_float2(v1.x, v1.y));
        __half2 h3 = __float22half2_rn(make_float2(v1.z, v1.w));
        uint4 u = make_uint4(*(unsigned*)&h0, *(unsigned*)&h1,
                             *(unsigned*)&h2, *(unsigned*)&h3);
        *(uint4*)(hs + m * 128 + ((c ^ (m & 7)) << 3)) = u;
    }
    #pragma unroll
    for (int i = 0; i < 8; i++) {
        int id = t + 256 * i;
        int ck = id >> 7;
        int nn = id & 127;
        float f[8];
        #pragma unroll
        for (int j = 0; j < 8; j++)
            f[j] = (nn < 100) ? Wa[(ck * 8 + j) * 100 + nn] : 0.f;
        __half2 h0 = __float22half2_rn(make_float2(f[0], f[1]));
        __half2 h1 = __float22half2_rn(make_float2(f[2], f[3]));
        __half2 h2 = __float22half2_rn(make_float2(f[4], f[5]));
        __half2 h3 = __float22half2_rn(make_float2(f[6], f[7]));
        uint4 u = make_uint4(*(unsigned*)&h0, *(unsigned*)&h1,
                             *(unsigned*)&h2, *(unsigned*)&h3);
        *(uint4*)(wt + nn * 128 + ((ck ^ (nn & 7)) << 3)) = u;
    }
    if (t < 128) bas[t] = (t < 100) ? ba[t] : -1e30f;
    __syncthreads();

    const int wid = t >> 5, lane = t & 31;
    const int wm = wid * 16;

    float acc[16][4];
    #pragma unroll
    for (int nt = 0; nt < 16; nt++)
        #pragma unroll
        for (int j = 0; j < 4; j++) acc[nt][j] = 0.f;

    const unsigned hs_base = (unsigned)__cvta_generic_to_shared(hs);
    const unsigned wt_base = (unsigned)__cvta_generic_to_shared(wt);
    const int ra = lane & 15;
    const int ka = lane >> 4;
    const int rbn = ((lane >> 4) << 3) + (lane & 7);
    const int kb  = (lane >> 3) & 1;

    #pragma unroll
    for (int ks = 0; ks < 8; ks++) {
        unsigned a[4];
        {
            int row = wm + ra;
            int c = ks * 2 + ka;
            unsigned addr = hs_base + ((row << 8) + ((c ^ (row & 7)) << 4));
            asm volatile("ldmatrix.sync.aligned.m8n8.x4.shared.b16 {%0,%1,%2,%3}, [%4];"
                : "=r"(a[0]), "=r"(a[1]), "=r"(a[2]), "=r"(a[3]) : "r"(addr));
        }
        #pragma unroll
        for (int np = 0; np < 8; np++) {
            unsigned b[4];
            int rn = np * 16 + rbn;
            int c = ks * 2 + kb;
            unsigned addr = wt_base + ((rn << 8) + ((c ^ (rn & 7)) << 4));
            asm volatile("ldmatrix.sync.aligned.m8n8.x4.shared.b16 {%0,%1,%2,%3}, [%4];"
                : "=r"(b[0]), "=r"(b[1]), "=r"(b[2]), "=r"(b[3]) : "r"(addr));
            #pragma unroll
            for (int half = 0; half < 2; half++) {
                int nt = np * 2 + half;
                asm volatile(
                    "mma.sync.aligned.m16n8k16.row.col.f32.f16.f16.f32 "
                    "{%0,%1,%2,%3}, {%4,%5,%6,%7}, {%8,%9}, {%0,%1,%2,%3};"
                    : "+f"(acc[nt][0]), "+f"(acc[nt][1]),
                      "+f"(acc[nt][2]), "+f"(acc[nt][3])
                    : "r"(a[0]), "r"(a[1]), "r"(a[2]), "r"(a[3]),
                      "r"(b[half * 2]), "r"(b[half * 2 + 1]));
            }
        }
    }

    float v0[32], v1[32];
    float mx0 = -1e30f, mx1 = -1e30f;
    #pragma unroll
    for (int nt = 0; nt < 16; nt++) {
        int c = nt * 8 + (lane & 3) * 2;
        float bb0 = bas[c], bb1 = bas[c + 1];
        v0[nt*2]   = acc[nt][0] + bb0;  v0[nt*2+1] = acc[nt][1] + bb1;
        v1[nt*2]   = acc[nt][2] + bb0;  v1[nt*2+1] = acc[nt][3] + bb1;
        mx0 = fmaxf(mx0, fmaxf(v0[nt*2], v0[nt*2+1]));
        mx1 = fmaxf(mx1, fmaxf(v1[nt*2], v1[nt*2+1]));
    }
    mx0 = fmaxf(mx0, __shfl_xor_sync(0xffffffffu, mx0, 1));
    mx0 = fmaxf(mx0, __shfl_xor_sync(0xffffffffu, mx0, 2));
    mx1 = fmaxf(mx1, __shfl_xor_sync(0xffffffffu, mx1, 1));
    mx1 = fmaxf(mx1, __shfl_xor_sync(0xffffffffu, mx1, 2));
    float sum0 = 0.f, sum1 = 0.f;
    #pragma unroll
    for (int j = 0; j < 32; j++) {
        v0[j] = expf(v0[j] - mx0); sum0 += v0[j];
        v1[j] = expf(v1[j] - mx1); sum1 += v1[j];
    }
    sum0 += __shfl_xor_sync(0xffffffffu, sum0, 1);
    sum0 += __shfl_xor_sync(0xffffffffu, sum0, 2);
    sum1 += __shfl_xor_sync(0xffffffffu, sum1, 1);
    sum1 += __shfl_xor_sync(0xffffffffu, sum1, 2);
    float inv0 = 1.0f / sum0, inv1 = 1.0f / sum1;

    int r0 = m0 + wm + (lane >> 2);
    int r1 = r0 + 8;
    #pragma unroll
    for (int nt = 0; nt < 16; nt++) {
        int c = nt * 8 + (lane & 3) * 2;
        if (c < 100) {
            if (r0 < n)
                *(float2*)(out + (size_t)r0 * 100 + c) =
                    make_float2(v0[nt*2] * inv0, v0[nt*2+1] * inv0);
            if (r1 < n)
                *(float2*)(out + (size_t)r1 * 100 + c) =
                    make_float2(v1[nt*2] * inv1, v1[nt*2+1] * inv1);
        }
    }
}

// ---------------------------------------------------------------------------
extern "C" void kernel_launch(void* const* d_in, const int* in_sizes, int n_in,
                              void* d_out, int out_size)
{
    int ix = 0, ie = 1, iW1 = 2, ib1 = 3, iW2 = 4, ib2 = 5, iWa = 6, iba = 7;
    {
        int jx=-1, je=-1, jW1=-1, jW2=-1, jb1=-1, jb2=-1, jWa=-1, jba=-1;
        for (int i = 0; i < n_in; i++) {
            int s = in_sizes[i];
            if      (s == 6400000) jx = i;
            else if (s == 3200000) je = i;
            else if (s == 16384)   { if (jW1 < 0) jW1 = i; else jW2 = i; }
            else if (s == 128)     { if (jb1 < 0) jb1 = i; else jb2 = i; }
            else if (s == 12800)   jWa = i;
            else if (s == 100)     jba = i;
        }
        if (jx>=0 && je>=0 && jW1>=0 && jW2>=0 && jb1>=0 && jb2>=0 && jWa>=0 && jba>=0) {
            ix=jx; ie=je; iW1=jW1; iW2=jW2; ib1=jb1; ib2=jb2; iWa=jWa; iba=jba;
        }
    }

    const float4* x   = (const float4*)d_in[ix];
    const void*   ei  = d_in[ie];
    const float*  W1  = (const float*)d_in[iW1];
    const float*  b1  = (const float*)d_in[ib1];
    const float*  W2  = (const float*)d_in[iW2];
    const float*  b2  = (const float*)d_in[ib2];
    const float*  Wa  = (const float*)d_in[iWa];
    const float*  ba  = (const float*)d_in[iba];
    float*        out = (float*)d_out;

    const int n = in_sizes[ix] / D;
    const int e = in_sizes[ie] / 2;

    uint2  *H;
    float4 *B2;
    float  *dinv;
    int *cnt, *rowptr, *cursor, *adj, *partials, *is64;
    cudaGetSymbolAddress((void**)&H, g_H);
    cudaGetSymbolAddress((void**)&B2, g_B2);
    cudaGetSymbolAddress((void**)&dinv, g_dinv);
    cudaGetSymbolAddress((void**)&cnt, g_cnt);
    cudaGetSymbolAddress((void**)&rowptr, g_rowptr);
    cudaGetSymbolAddress((void**)&cursor, g_cursor);
    cudaGetSymbolAddress((void**)&adj, g_adj);
    cudaGetSymbolAddress((void**)&partials, g_partials);
    cudaGetSymbolAddress((void**)&is64, g_is64);

    const int SMEM_TC    = 2 * 128 * 128 * 2;
    const int SMEM_FINAL = 2 * 128 * 128 * 2 + 128 * 4;
    cudaFuncSetAttribute(k_gemm128t, cudaFuncAttributeMaxDynamicSharedMemorySize, SMEM_TC);
    cudaFuncSetAttribute(k_final_tc, cudaFuncAttributeMaxDynamicSharedMemorySize, SMEM_FINAL);

    const int gemm_blocks = (n + 127) / 128;
    const int nb = (n + 255) / 256;
    const int e4b = ((e + 3) / 4 + 255) / 256;   // 4 edges/thread kernels
    const int gb = (n * 32 + 255) / 256;
    const int scan_blocks = (n + SCAN_TILE - 1) / SCAN_TILE;

    // CSR build (dtype-robust, vectorized edge streaming)
    k_detect<<<1, 256>>>((const unsigned int*)ei, is64);
    k_zero_cnt<<<nb, 256>>>(cnt, n);
    k_count<<<e4b, 256>>>(ei, is64, cnt, e);
    k_scan_partial<<<scan_blocks, 256>>>(cnt, partials, n);
    k_scan_offsets<<<1, MAX_PARTIALS>>>(partials, rowptr, scan_blocks, n);
    k_scan_final<<<scan_blocks, 256>>>(cnt, partials, rowptr, cursor, dinv, n);
    k_fill<<<e4b, 256>>>(ei, is64, cursor, adj, e);

    // layer 1
    k_gemm128t<<<gemm_blocks, 256, SMEM_TC>>>(x, W1, dinv, H, n);
    k_gather<<<gb, 256>>>((const uint4*)H, rowptr, adj, dinv, b1, B2, n, 1);

    // layer 2
    k_gemm128t<<<gemm_blocks, 256, SMEM_TC>>>(B2, W2, dinv, H, n);
    k_gather<<<gb, 256>>>((const uint4*)H, rowptr, adj, dinv, b2, B2, n, 0);

    // head + softmax (tensor core)
    k_final_tc<<<gemm_blocks, 256, SMEM_FINAL>>>(B2, Wa, ba, out, n);
}

// round 11
// speedup vs baseline: 6.8189x; 1.0548x over previous
#include <cuda_runtime.h>
#include <cuda_fp16.h>

// Problem constants
#define D 128
#define NMAX 50000
#define EMAX 1600000
#define SCAN_TILE 1024
#define MAX_PARTIALS 256

// Scratch (uint4 => 16B alignment guaranteed for vector LDG/STG)
__device__ uint4  g_H[NMAX * 16];    // pre-scaled linear output, fp16 (16 halves/uint4 x16)
__device__ uint4  g_B2[NMAX * 16];   // layer activation, fp16
__device__ float  g_dinv[NMAX];
__device__ int    g_cnt[NMAX];
__device__ int    g_rowptr[NMAX + 1];
__device__ int    g_cursor[NMAX];
__device__ int    g_adj[EMAX];
__device__ int    g_partials[MAX_PARTIALS];
__device__ int    g_is64;

// ---------------------------------------------------------------------------
__global__ void k_detect(const unsigned int* __restrict__ p, int* flag) {
    __shared__ unsigned int s;
    if (threadIdx.x == 0) s = 0u;
    __syncthreads();
    unsigned int v = p[threadIdx.x * 2 + 1];
    #pragma unroll
    for (int o = 16; o >= 1; o >>= 1) v |= __shfl_xor_sync(0xffffffffu, v, o);
    if ((threadIdx.x & 31) == 0) atomicOr(&s, v);
    __syncthreads();
    if (threadIdx.x == 0) *flag = (s == 0u) ? 1 : 0;
}

__global__ void k_zero_cnt(int* cnt, int n) {
    int i = blockIdx.x * blockDim.x + threadIdx.x;
    if (i < n) cnt[i] = 0;
}

// Count incoming edges, 4 edges/thread vectorized.
__global__ void k_count(const void* __restrict__ ei, const int* __restrict__ flag,
                        int* cnt, int e) {
    int i = (blockIdx.x * blockDim.x + threadIdx.x) * 4;
    if (i >= e) return;
    int e4 = e & ~3;
    if (*flag) {
        const long long* base = (const long long*)ei + e;
        if (i < e4 && (e & 1) == 0) {
            const longlong2* p = (const longlong2*)base;
            longlong2 a = p[i >> 1];
            longlong2 b = p[(i >> 1) + 1];
            atomicAdd(&cnt[(int)a.x], 1);
            atomicAdd(&cnt[(int)a.y], 1);
            atomicAdd(&cnt[(int)b.x], 1);
            atomicAdd(&cnt[(int)b.y], 1);
        } else {
            for (int j = i; j < e && j < i + 4; j++)
                atomicAdd(&cnt[(int)base[j]], 1);
        }
        if (i == 0) {
            for (int j = e4; j < e; j++) atomicAdd(&cnt[(int)base[j]], 1);
        }
    } else {
        const int* base = (const int*)ei + e;
        if (i < e4 && (e & 3) == 0) {
            int4 d = ((const int4*)base)[i >> 2];
            atomicAdd(&cnt[d.x], 1);
            atomicAdd(&cnt[d.y], 1);
            atomicAdd(&cnt[d.z], 1);
            atomicAdd(&cnt[d.w], 1);
        } else {
            for (int j = i; j < e && j < i + 4; j++)
                atomicAdd(&cnt[base[j]], 1);
        }
    }
}

__global__ void k_dinv(const int* __restrict__ cnt, float* dinv, int n) {
    int i = blockIdx.x * blockDim.x + threadIdx.x;
    if (i < n) dinv[i] = rsqrtf((float)(cnt[i] + 1));   // +1 self-loop
}

// ---------------------------------------------------------------------------
__global__ void k_scan_partial(const int* __restrict__ cnt, int* __restrict__ partials, int n) {
    __shared__ int ws[8];
    const int lane = threadIdx.x & 31, wid = threadIdx.x >> 5;
    int i0 = blockIdx.x * SCAN_TILE + threadIdx.x * 4;
    int s = 0;
    #pragma unroll
    for (int j = 0; j < 4; j++) {
        int i = i0 + j;
        if (i < n) s += cnt[i];
    }
    #pragma unroll
    for (int o = 16; o >= 1; o >>= 1) s += __shfl_xor_sync(0xffffffffu, s, o);
    if (lane == 0) ws[wid] = s;
    __syncthreads();
    if (threadIdx.x == 0) {
        int t = 0;
        #pragma unroll
        for (int j = 0; j < 8; j++) t += ws[j];
        partials[blockIdx.x] = t;
    }
}

__global__ void k_scan_offsets(int* __restrict__ partials, int* __restrict__ row_ptr,
                               int nblk, int n) {
    __shared__ int sh[MAX_PARTIALS];
    int t = threadIdx.x;
    int v = (t < nblk) ? partials[t] : 0;
    sh[t] = v;
    __syncthreads();
    #pragma unroll
    for (int o = 1; o < MAX_PARTIALS; o <<= 1) {
        int y = (t >= o) ? sh[t - o] : 0;
        __syncthreads();
        sh[t] += y;
        __syncthreads();
    }
    if (t < nblk) partials[t] = sh[t] - v;
    if (t == nblk - 1) row_ptr[n] = sh[t];
}

__global__ void k_scan_final(const int* __restrict__ cnt, const int* __restrict__ partials,
                             int* __restrict__ row_ptr, int* __restrict__ cursor, int n) {
    __shared__ int ws[8];
    const int lane = threadIdx.x & 31, wid = threadIdx.x >> 5;
    int i0 = blockIdx.x * SCAN_TILE + threadIdx.x * 4;
    int v[4], s = 0;
    #pragma unroll
    for (int j = 0; j < 4; j++) {
        int i = i0 + j;
        v[j] = (i < n) ? cnt[i] : 0;
        s += v[j];
    }
    int x = s;
    #pragma unroll
    for (int o = 1; o < 32; o <<= 1) {
        int y = __shfl_up_sync(0xffffffffu, x, o);
        if (lane >= o) x += y;
    }
    if (lane == 31) ws[wid] = x;
    __syncthreads();
    int warp_off = 0;
    if (wid > 0) {
        #pragma unroll
        for (int j = 0; j < 7; j++) if (j < wid) warp_off += ws[j];
    }
    int run = partials[blockIdx.x] + warp_off + x - s;
    #pragma unroll
    for (int j = 0; j < 4; j++) {
        int i = i0 + j;
        if (i < n) {
            row_ptr[i] = run;
            cursor[i]  = run;
            run += v[j];
        }
    }
}

// Bin edges into CSR, 4 edges/thread vectorized.
__global__ void k_fill(const void* __restrict__ ei, const int* __restrict__ flag,
                       int* cursor, int* __restrict__ adj, int e) {
    int i = (blockIdx.x * blockDim.x + threadIdx.x) * 4;
    if (i >= e) return;
    int e4 = e & ~3;
    int sv[4], dv[4], cnt4 = 0;
    if (*flag) {
        const long long* sb = (const long long*)ei;
        const long long* db = sb + e;
        if (i < e4 && (e & 1) == 0) {
            const longlong2* sp = (const longlong2*)sb;
            const longlong2* dp = (const longlong2*)db;
            longlong2 s0 = sp[i >> 1], s1 = sp[(i >> 1) + 1];
            longlong2 d0 = dp[i >> 1], d1 = dp[(i >> 1) + 1];
            sv[0]=(int)s0.x; sv[1]=(int)s0.y; sv[2]=(int)s1.x; sv[3]=(int)s1.y;
            dv[0]=(int)d0.x; dv[1]=(int)d0.y; dv[2]=(int)d1.x; dv[3]=(int)d1.y;
            cnt4 = 4;
        } else {
            for (int j = i; j < e && j < i + 4; j++) {
                sv[cnt4] = (int)sb[j]; dv[cnt4] = (int)db[j]; cnt4++;
            }
        }
        if (i == 0) {
            for (int j = e4; j < e; j++) {
                int pos = atomicAdd(&cursor[(int)db[j]], 1);
                adj[pos] = (int)sb[j];
            }
        }
    } else {
        const int* sb = (const int*)ei;
        const int* db = sb + e;
        if (i < e4 && (e & 3) == 0) {
            int4 s4 = ((const int4*)sb)[i >> 2];
            int4 d4 = ((const int4*)db)[i >> 2];
            sv[0]=s4.x; sv[1]=s4.y; sv[2]=s4.z; sv[3]=s4.w;
            dv[0]=d4.x; dv[1]=d4.y; dv[2]=d4.z; dv[3]=d4.w;
            cnt4 = 4;
        } else {
            for (int j = i; j < e && j < i + 4; j++) {
                sv[cnt4] = sb[j]; dv[cnt4] = db[j]; cnt4++;
            }
        }
    }
    #pragma unroll
    for (int j = 0; j < 4; j++) {
        if (j < cnt4) {
            int pos = atomicAdd(&cursor[dv[j]], 1);
            adj[pos] = sv[j];
        }
    }
}

// ---------------------------------------------------------------------------
// Shared HMMA mainloop pieces for the 128x128x128 tile kernels.
// Tensor-core GEMM (fp32 A input): C = half((A @ W) * scale[m])
__global__ void __launch_bounds__(256, 1)
k_gemm128t(const float4* __restrict__ A, const float* __restrict__ W,
           const float* __restrict__ scale, uint4* __restrict__ C, int n)
{
    extern __shared__ __half smh[];
    __half* as = smh;
    __half* bt = smh + 16384;
    const int m0 = blockIdx.x * 128;
    const int t  = threadIdx.x;

    #pragma unroll
    for (int i = 0; i < 8; i++) {
        int id = t + 256 * i;
        int m = id >> 4, c = id & 15;
        float4 v0 = make_float4(0.f,0.f,0.f,0.f), v1 = v0;
        if (m0 + m < n) {
            v0 = A[(size_t)(m0 + m) * 32 + c * 2];
            v1 = A[(size_t)(m0 + m) * 32 + c * 2 + 1];
        }
        __half2 h0 = __float22half2_rn(make_float2(v0.x, v0.y));
        __half2 h1 = __float22half2_rn(make_float2(v0.z, v0.w));
        __half2 h2 = __float22half2_rn(make_float2(v1.x, v1.y));
        __half2 h3 = __float22half2_rn(make_float2(v1.z, v1.w));
        uint4 u = make_uint4(*(unsigned*)&h0, *(unsigned*)&h1,
                             *(unsigned*)&h2, *(unsigned*)&h3);
        *(uint4*)(as + m * 128 + ((c ^ (m & 7)) << 3)) = u;
    }
    #pragma unroll
    for (int i = 0; i < 8; i++) {
        int id = t + 256 * i;
        int ck = id >> 7;
        int nn = id & 127;
        float f[8];
        #pragma unroll
        for (int j = 0; j < 8; j++) f[j] = W[(ck * 8 + j) * 128 + nn];
        __half2 h0 = __float22half2_rn(make_float2(f[0], f[1]));
        __half2 h1 = __float22half2_rn(make_float2(f[2], f[3]));
        __half2 h2 = __float22half2_rn(make_float2(f[4], f[5]));
        __half2 h3 = __float22half2_rn(make_float2(f[6], f[7]));
        uint4 u = make_uint4(*(unsigned*)&h0, *(unsigned*)&h1,
                             *(unsigned*)&h2, *(unsigned*)&h3);
        *(uint4*)(bt + nn * 128 + ((ck ^ (nn & 7)) << 3)) = u;
    }
    __syncthreads();

    const int wid = t >> 5, lane = t & 31;
    const int wm = (wid >> 1) * 32;
    const int wn = (wid & 1) * 64;

    float acc[2][8][4];
    #pragma unroll
    for (int mt = 0; mt < 2; mt++)
        #pragma unroll
        for (int nt = 0; nt < 8; nt++)
            #pragma unroll
            for (int j = 0; j < 4; j++) acc[mt][nt][j] = 0.f;

    const unsigned as_base = (unsigned)__cvta_generic_to_shared(as);
    const unsigned bt_base = (unsigned)__cvta_generic_to_shared(bt);
    const int ra = lane & 15;
    const int ka = lane >> 4;
    const int rbn = ((lane >> 4) << 3) + (lane & 7);
    const int kb  = (lane >> 3) & 1;

    #pragma unroll
    for (int ks = 0; ks < 8; ks++) {
        unsigned a[2][4];
        #pragma unroll
        for (int mt = 0; mt < 2; mt++) {
            int row = wm + mt * 16 + ra;
            int c = ks * 2 + ka;
            unsigned addr = as_base + ((row << 8) + ((c ^ (row & 7)) << 4));
            asm volatile("ldmatrix.sync.aligned.m8n8.x4.shared.b16 {%0,%1,%2,%3}, [%4];"
                : "=r"(a[mt][0]), "=r"(a[mt][1]), "=r"(a[mt][2]), "=r"(a[mt][3])
                : "r"(addr));
        }
        unsigned b[4][4];
        #pragma unroll
        for (int np = 0; np < 4; np++) {
            int rn = wn + np * 16 + rbn;
            int c = ks * 2 + kb;
            unsigned addr = bt_base + ((rn << 8) + ((c ^ (rn & 7)) << 4));
            asm volatile("ldmatrix.sync.aligned.m8n8.x4.shared.b16 {%0,%1,%2,%3}, [%4];"
                : "=r"(b[np][0]), "=r"(b[np][1]), "=r"(b[np][2]), "=r"(b[np][3])
                : "r"(addr));
        }
        #pragma unroll
        for (int mt = 0; mt < 2; mt++)
            #pragma unroll
            for (int nt = 0; nt < 8; nt++) {
                unsigned b0 = b[nt >> 1][(nt & 1) * 2];
                unsigned b1 = b[nt >> 1][(nt & 1) * 2 + 1];
                asm volatile(
                    "mma.sync.aligned.m16n8k16.row.col.f32.f16.f16.f32 "
                    "{%0,%1,%2,%3}, {%4,%5,%6,%7}, {%8,%9}, {%0,%1,%2,%3};"
                    : "+f"(acc[mt][nt][0]), "+f"(acc[mt][nt][1]),
                      "+f"(acc[mt][nt][2]), "+f"(acc[mt][nt][3])
                    : "r"(a[mt][0]), "r"(a[mt][1]), "r"(a[mt][2]), "r"(a[mt][3]),
                      "r"(b0), "r"(b1));
            }
    }

    __half2* C2 = (__half2*)C;
    #pragma unroll
    for (int mt = 0; mt < 2; mt++) {
        int row0 = m0 + wm + mt * 16 + (lane >> 2);
        int row1 = row0 + 8;
        float s0 = (row0 < n) ? scale[row0] : 0.f;
        float s1 = (row1 < n) ? scale[row1] : 0.f;
        #pragma unroll
        for (int nt = 0; nt < 8; nt++) {
            int cp = (wn + nt * 8) / 2 + (lane & 3);
            if (row0 < n) {
                __half2 h = __float22half2_rn(
                    make_float2(acc[mt][nt][0] * s0, acc[mt][nt][1] * s0));
                C2[(size_t)row0 * 64 + cp] = h;
            }
            if (row1 < n) {
                __half2 h = __float22half2_rn(
                    make_float2(acc[mt][nt][2] * s1, acc[mt][nt][3] * s1));
                C2[(size_t)row1 * 64 + cp] = h;
            }
        }
    }
}

// Tensor-core GEMM (fp16 A input, 16 uint4 per row): C = half((A @ W) * scale[m])
__global__ void __launch_bounds__(256, 1)
k_gemm128th(const uint4* __restrict__ A16, const float* __restrict__ W,
            const float* __restrict__ scale, uint4* __restrict__ C, int n)
{
    extern __shared__ __half smh[];
    __half* as = smh;
    __half* bt = smh + 16384;
    const int m0 = blockIdx.x * 128;
    const int t  = threadIdx.x;

    #pragma unroll
    for (int i = 0; i < 8; i++) {
        int id = t + 256 * i;
        int m = id >> 4, c = id & 15;
        uint4 u = make_uint4(0u,0u,0u,0u);
        if (m0 + m < n) u = A16[(size_t)(m0 + m) * 16 + c];
        *(uint4*)(as + m * 128 + ((c ^ (m & 7)) << 3)) = u;
    }
    #pragma unroll
    for (int i = 0; i < 8; i++) {
        int id = t + 256 * i;
        int ck = id >> 7;
        int nn = id & 127;
        float f[8];
        #pragma unroll
        for (int j = 0; j < 8; j++) f[j] = W[(ck * 8 + j) * 128 + nn];
        __half2 h0 = __float22half2_rn(make_float2(f[0], f[1]));
        __half2 h1 = __float22half2_rn(make_float2(f[2], f[3]));
        __half2 h2 = __float22half2_rn(make_float2(f[4], f[5]));
        __half2 h3 = __float22half2_rn(make_float2(f[6], f[7]));
        uint4 u = make_uint4(*(unsigned*)&h0, *(unsigned*)&h1,
                             *(unsigned*)&h2, *(unsigned*)&h3);
        *(uint4*)(bt + nn * 128 + ((ck ^ (nn & 7)) << 3)) = u;
    }
    __syncthreads();

    const int wid = t >> 5, lane = t & 31;
    const int wm = (wid >> 1) * 32;
    const int wn = (wid & 1) * 64;

    float acc[2][8][4];
    #pragma unroll
    for (int mt = 0; mt < 2; mt++)
        #pragma unroll
        for (int nt = 0; nt < 8; nt++)
            #pragma unroll
            for (int j = 0; j < 4; j++) acc[mt][nt][j] = 0.f;

    const unsigned as_base = (unsigned)__cvta_generic_to_shared(as);
    const unsigned bt_base = (unsigned)__cvta_generic_to_shared(bt);
    const int ra = lane & 15;
    const int ka = lane >> 4;
    const int rbn = ((lane >> 4) << 3) + (lane & 7);
    const int kb  = (lane >> 3) & 1;

    #pragma unroll
    for (int ks = 0; ks < 8; ks++) {
        unsigned a[2][4];
        #pragma unroll
        for (int mt = 0; mt < 2; mt++) {
            int row = wm + mt * 16 + ra;
            int c = ks * 2 + ka;
            unsigned addr = as_base + ((row << 8) + ((c ^ (row & 7)) << 4));
            asm volatile("ldmatrix.sync.aligned.m8n8.x4.shared.b16 {%0,%1,%2,%3}, [%4];"
                : "=r"(a[mt][0]), "=r"(a[mt][1]), "=r"(a[mt][2]), "=r"(a[mt][3])
                : "r"(addr));
        }
        unsigned b[4][4];
        #pragma unroll
        for (int np = 0; np < 4; np++) {
            int rn = wn + np * 16 + rbn;
            int c = ks * 2 + kb;
            unsigned addr = bt_base + ((rn << 8) + ((c ^ (rn & 7)) << 4));
            asm volatile("ldmatrix.sync.aligned.m8n8.x4.shared.b16 {%0,%1,%2,%3}, [%4];"
                : "=r"(b[np][0]), "=r"(b[np][1]), "=r"(b[np][2]), "=r"(b[np][3])
                : "r"(addr));
        }
        #pragma unroll
        for (int mt = 0; mt < 2; mt++)
            #pragma unroll
            for (int nt = 0; nt < 8; nt++) {
                unsigned b0 = b[nt >> 1][(nt & 1) * 2];
                unsigned b1 = b[nt >> 1][(nt & 1) * 2 + 1];
                asm volatile(
                    "mma.sync.aligned.m16n8k16.row.col.f32.f16.f16.f32 "
                    "{%0,%1,%2,%3}, {%4,%5,%6,%7}, {%8,%9}, {%0,%1,%2,%3};"
                    : "+f"(acc[mt][nt][0]), "+f"(acc[mt][nt][1]),
                      "+f"(acc[mt][nt][2]), "+f"(acc[mt][nt][3])
                    : "r"(a[mt][0]), "r"(a[mt][1]), "r"(a[mt][2]), "r"(a[mt][3]),
                      "r"(b0), "r"(b1));
            }
    }

    __half2* C2 = (__half2*)C;
    #pragma unroll
    for (int mt = 0; mt < 2; mt++) {
        int row0 = m0 + wm + mt * 16 + (lane >> 2);
        int row1 = row0 + 8;
        float s0 = (row0 < n) ? scale[row0] : 0.f;
        float s1 = (row1 < n) ? scale[row1] : 0.f;
        #pragma unroll
        for (int nt = 0; nt < 8; nt++) {
            int cp = (wn + nt * 8) / 2 + (lane & 3);
            if (row0 < n) {
                __half2 h = __float22half2_rn(
                    make_float2(acc[mt][nt][0] * s0, acc[mt][nt][1] * s0));
                C2[(size_t)row0 * 64 + cp] = h;
            }
            if (row1 < n) {
                __half2 h = __float22half2_rn(
                    make_float2(acc[mt][nt][2] * s1, acc[mt][nt][3] * s1));
                C2[(size_t)row1 * 64 + cp] = h;
            }
        }
    }
}

// ---------------------------------------------------------------------------
__device__ __forceinline__ void acc_add8(float4& a, float4& b, uint4 v) {
    float2 f0 = __half22float2(*(__half2*)&v.x);
    float2 f1 = __half22float2(*(__half2*)&v.y);
    float2 f2 = __half22float2(*(__half2*)&v.z);
    float2 f3 = __half22float2(*(__half2*)&v.w);
    a.x += f0.x; a.y += f0.y; a.z += f1.x; a.w += f1.y;
    b.x += f2.x; b.y += f2.y; b.z += f3.x; b.w += f3.y;
}

// Fused aggregation: warp/node; half-warps split even/odd edges; fp16 output.
__global__ void __launch_bounds__(256)
k_gather(const uint4* __restrict__ h4, const int* __restrict__ row_ptr,
         const int* __restrict__ adj, const float* __restrict__ dinv,
         const float* __restrict__ b, uint2* __restrict__ out, int n, int relu)
{
    int w = (blockIdx.x * 256 + threadIdx.x) >> 5;
    int lane = threadIdx.x & 31;
    if (w >= n) return;
    const int half = lane >> 4, cl = lane & 15;
    int beg = __ldg(&row_ptr[w]);
    int end = __ldg(&row_ptr[w + 1]);

    float4 accA = make_float4(0.f,0.f,0.f,0.f);
    float4 accB = make_float4(0.f,0.f,0.f,0.f);
    if (half == 0) acc_add8(accA, accB, h4[(size_t)w * 16 + cl]);   // self-loop

    int i = beg + half;
    for (; i + 2 < end; i += 4) {
        int s0 = __ldg(&adj[i]);
        int s1 = __ldg(&adj[i + 2]);
        uint4 v0 = h4[(size_t)s0 * 16 + cl];
        uint4 v1 = h4[(size_t)s1 * 16 + cl];
        acc_add8(accA, accB, v0);
        acc_add8(accA, accB, v1);
    }
    for (; i < end; i += 2) {
        int s0 = __ldg(&adj[i]);
        acc_add8(accA, accB, h4[(size_t)s0 * 16 + cl]);
    }

    accA.x += __shfl_xor_sync(0xffffffffu, accA.x, 16);
    accA.y += __shfl_xor_sync(0xffffffffu, accA.y, 16);
    accA.z += __shfl_xor_sync(0xffffffffu, accA.z, 16);
    accA.w += __shfl_xor_sync(0xffffffffu, accA.w, 16);
    accB.x += __shfl_xor_sync(0xffffffffu, accB.x, 16);
    accB.y += __shfl_xor_sync(0xffffffffu, accB.y, 16);
    accB.z += __shfl_xor_sync(0xffffffffu, accB.z, 16);
    accB.w += __shfl_xor_sync(0xffffffffu, accB.w, 16);

    float sc = dinv[w];
    float4 acc = (half == 0) ? accA : accB;
    float4 bb = ((const float4*)b)[cl * 2 + half];
    float4 r;
    r.x = acc.x * sc + bb.x;
    r.y = acc.y * sc + bb.y;
    r.z = acc.z * sc + bb.z;
    r.w = acc.w * sc + bb.w;
    if (relu) {
        r.x = fmaxf(r.x, 0.f); r.y = fmaxf(r.y, 0.f);
        r.z = fmaxf(r.z, 0.f); r.w = fmaxf(r.w, 0.f);
    }
    __half2 p0 = __float22half2_rn(make_float2(r.x, r.y));
    __half2 p1 = __float22half2_rn(make_float2(r.z, r.w));
    out[(size_t)w * 32 + cl * 2 + half] = make_uint2(*(unsigned*)&p0, *(unsigned*)&p1);
}

// ---------------------------------------------------------------------------
// Tensor-core head (fp16 H input): out = softmax(H @ Wa + ba).
__global__ void __launch_bounds__(256, 1)
k_final_tc(const uint4* __restrict__ H16, const float* __restrict__ Wa,
           const float* __restrict__ ba, float* __restrict__ out, int n)
{
    extern __shared__ __half smh[];
    __half* hs = smh;
    __half* wt = smh + 16384;
    float*  bas = (float*)(smh + 32768);
    const int m0 = blockIdx.x * 128;
    const int t  = threadIdx.x;

    #pragma unroll
    for (int i = 0; i < 8; i++) {
        int id = t + 256 * i;
        int m = id >> 4, c = id & 15;
        uint4 u = make_uint4(0u,0u,0u,0u);
        if (m0 + m < n) u = H16[(size_t)(m0 + m) * 16 + c];
        *(uint4*)(hs + m * 128 + ((c ^ (m & 7)) << 3)) = u;
    }
    #pragma unroll
    for (int i = 0; i < 8; i++) {
        int id = t + 256 * i;
        int ck = id >> 7;
        int nn = id & 127;
        float f[8];
        #pragma unroll
        for (int j = 0; j < 8; j++)
            f[j] = (nn < 100) ? Wa[(ck * 8 + j) * 100 + nn] : 0.f;
        __half2 h0 = __float22half2_rn(make_float2(f[0], f[1]));
        __half2 h1 = __float22half2_rn(make_float2(f[2], f[3]));
        __half2 h2 = __float22half2_rn(make_float2(f[4], f[5]));
        __half2 h3 = __float22half2_rn(make_float2(f[6], f[7]));
        uint4 u = make_uint4(*(unsigned*)&h0, *(unsigned*)&h1,
                             *(unsigned*)&h2, *(unsigned*)&h3);
        *(uint4*)(wt + nn * 128 + ((ck ^ (nn & 7)) << 3)) = u;
    }
    if (t < 128) bas[t] = (t < 100) ? ba[t] : -1e30f;
    __syncthreads();

    const int wid = t >> 5, lane = t & 31;
    const int wm = wid * 16;

    float acc[16][4];
    #pragma unroll
    for (int nt = 0; nt < 16; nt++)
        #pragma unroll
        for (int j = 0; j < 4; j++) acc[nt][j] = 0.f;

    const unsigned hs_base = (unsigned)__cvta_generic_to_shared(hs);
    const unsigned wt_base = (unsigned)__cvta_generic_to_shared(wt);
    const int ra = lane & 15;
    const int ka = lane >> 4;
    const int rbn = ((lane >> 4) << 3) + (lane & 7);
    const int kb  = (lane >> 3) & 1;

    #pragma unroll
    for (int ks = 0; ks < 8; ks++) {
        unsigned a[4];
        {
            int row = wm + ra;
            int c = ks * 2 + ka;
            unsigned addr = hs_base + ((row << 8) + ((c ^ (row & 7)) << 4));
            asm volatile("ldmatrix.sync.aligned.m8n8.x4.shared.b16 {%0,%1,%2,%3}, [%4];"
                : "=r"(a[0]), "=r"(a[1]), "=r"(a[2]), "=r"(a[3]) : "r"(addr));
        }
        #pragma unroll
        for (int np = 0; np < 8; np++) {
            unsigned b[4];
            int rn = np * 16 + rbn;
            int c = ks * 2 + kb;
            unsigned addr = wt_base + ((rn << 8) + ((c ^ (rn & 7)) << 4));
            asm volatile("ldmatrix.sync.aligned.m8n8.x4.shared.b16 {%0,%1,%2,%3}, [%4];"
                : "=r"(b[0]), "=r"(b[1]), "=r"(b[2]), "=r"(b[3]) : "r"(addr));
            #pragma unroll
            for (int half = 0; half < 2; half++) {
                int nt = np * 2 + half;
                asm volatile(
                    "mma.sync.aligned.m16n8k16.row.col.f32.f16.f16.f32 "
                    "{%0,%1,%2,%3}, {%4,%5,%6,%7}, {%8,%9}, {%0,%1,%2,%3};"
                    : "+f"(acc[nt][0]), "+f"(acc[nt][1]),
                      "+f"(acc[nt][2]), "+f"(acc[nt][3])
                    : "r"(a[0]), "r"(a[1]), "r"(a[2]), "r"(a[3]),
                      "r"(b[half * 2]), "r"(b[half * 2 + 1]));
            }
        }
    }

    float v0[32], v1[32];
    float mx0 = -1e30f, mx1 = -1e30f;
    #pragma unroll
    for (int nt = 0; nt < 16; nt++) {
        int c = nt * 8 + (lane & 3) * 2;
        float bb0 = bas[c], bb1 = bas[c + 1];
        v0[nt*2]   = acc[nt][0] + bb0;  v0[nt*2+1] = acc[nt][1] + bb1;
        v1[nt*2]   = acc[nt][2] + bb0;  v1[nt*2+1] = acc[nt][3] + bb1;
        mx0 = fmaxf(mx0, fmaxf(v0[nt*2], v0[nt*2+1]));
        mx1 = fmaxf(mx1, fmaxf(v1[nt*2], v1[nt*2+1]));
    }
    mx0 = fmaxf(mx0, __shfl_xor_sync(0xffffffffu, mx0, 1));
    mx0 = fmaxf(mx0, __shfl_xor_sync(0xffffffffu, mx0, 2));
    mx1 = fmaxf(mx1, __shfl_xor_sync(0xffffffffu, mx1, 1));
    mx1 = fmaxf(mx1, __shfl_xor_sync(0xffffffffu, mx1, 2));
    float sum0 = 0.f, sum1 = 0.f;
    #pragma unroll
    for (int j = 0; j < 32; j++) {
        v0[j] = expf(v0[j] - mx0); sum0 += v0[j];
        v1[j] = expf(v1[j] - mx1); sum1 += v1[j];
    }
    sum0 += __shfl_xor_sync(0xffffffffu, sum0, 1);
    sum0 += __shfl_xor_sync(0xffffffffu, sum0, 2);
    sum1 += __shfl_xor_sync(0xffffffffu, sum1, 1);
    sum1 += __shfl_xor_sync(0xffffffffu, sum1, 2);
    float inv0 = 1.0f / sum0, inv1 = 1.0f / sum1;

    int r0 = m0 + wm + (lane >> 2);
    int r1 = r0 + 8;
    #pragma unroll
    for (int nt = 0; nt < 16; nt++) {
        int c = nt * 8 + (lane & 3) * 2;
        if (c < 100) {
            if (r0 < n)
                *(float2*)(out + (size_t)r0 * 100 + c) =
                    make_float2(v0[nt*2] * inv0, v0[nt*2+1] * inv0);
            if (r1 < n)
                *(float2*)(out + (size_t)r1 * 100 + c) =
                    make_float2(v1[nt*2] * inv1, v1[nt*2+1] * inv1);
        }
    }
}

// ---------------------------------------------------------------------------
extern "C" void kernel_launch(void* const* d_in, const int* in_sizes, int n_in,
                              void* d_out, int out_size)
{
    int ix = 0, ie = 1, iW1 = 2, ib1 = 3, iW2 = 4, ib2 = 5, iWa = 6, iba = 7;
    {
        int jx=-1, je=-1, jW1=-1, jW2=-1, jb1=-1, jb2=-1, jWa=-1, jba=-1;
        for (int i = 0; i < n_in; i++) {
            int s = in_sizes[i];
            if      (s == 6400000) jx = i;
            else if (s == 3200000) je = i;
            else if (s == 16384)   { if (jW1 < 0) jW1 = i; else jW2 = i; }
            else if (s == 128)     { if (jb1 < 0) jb1 = i; else jb2 = i; }
            else if (s == 12800)   jWa = i;
            else if (s == 100)     jba = i;
        }
        if (jx>=0 && je>=0 && jW1>=0 && jW2>=0 && jb1>=0 && jb2>=0 && jWa>=0 && jba>=0) {
            ix=jx; ie=je; iW1=jW1; iW2=jW2; ib1=jb1; ib2=jb2; iWa=jWa; iba=jba;
        }
    }

    const float4* x   = (const float4*)d_in[ix];
    const void*   ei  = d_in[ie];
    const float*  W1  = (const float*)d_in[iW1];
    const float*  b1  = (const float*)d_in[ib1];
    const float*  W2  = (const float*)d_in[iW2];
    const float*  b2  = (const float*)d_in[ib2];
    const float*  Wa  = (const float*)d_in[iWa];
    const float*  ba  = (const float*)d_in[iba];
    float*        out = (float*)d_out;

    const int n = in_sizes[ix] / D;
    const int e = in_sizes[ie] / 2;

    uint4 *H, *B2;
    float *dinv;
    int *cnt, *rowptr, *cursor, *adj, *partials, *is64;
    cudaGetSymbolAddress((void**)&H, g_H);
    cudaGetSymbolAddress((void**)&B2, g_B2);
    cudaGetSymbolAddress((void**)&dinv, g_dinv);
    cudaGetSymbolAddress((void**)&cnt, g_cnt);
    cudaGetSymbolAddress((void**)&rowptr, g_rowptr);
    cudaGetSymbolAddress((void**)&cursor, g_cursor);
    cudaGetSymbolAddress((void**)&adj, g_adj);
    cudaGetSymbolAddress((void**)&partials, g_partials);
    cudaGetSymbolAddress((void**)&is64, g_is64);

    const int SMEM_TC    = 2 * 128 * 128 * 2;
    const int SMEM_FINAL = 2 * 128 * 128 * 2 + 128 * 4;
    cudaFuncSetAttribute(k_gemm128t,  cudaFuncAttributeMaxDynamicSharedMemorySize, SMEM_TC);
    cudaFuncSetAttribute(k_gemm128th, cudaFuncAttributeMaxDynamicSharedMemorySize, SMEM_TC);
    cudaFuncSetAttribute(k_final_tc,  cudaFuncAttributeMaxDynamicSharedMemorySize, SMEM_FINAL);

    const int gemm_blocks = (n + 127) / 128;
    const int nb = (n + 255) / 256;
    const int e4b = ((e + 3) / 4 + 255) / 256;
    const int gb = (n * 32 + 255) / 256;
    const int scan_blocks = (n + SCAN_TILE - 1) / SCAN_TILE;

    // Try to fork GEMM-1 onto a side stream, overlapping with scan+fill.
    cudaStream_t s1 = 0;
    cudaEvent_t evA = 0, evB = 0;
    bool par = (cudaStreamCreateWithFlags(&s1, cudaStreamNonBlocking) == cudaSuccess);
    if (par) par = (cudaEventCreateWithFlags(&evA, cudaEventDisableTiming) == cudaSuccess);
    if (par) par = (cudaEventCreateWithFlags(&evB, cudaEventDisableTiming) == cudaSuccess);

    // Common prefix: decode + degree count + dinv (stream 0)
    k_detect<<<1, 256>>>((const unsigned int*)ei, is64);
    k_zero_cnt<<<nb, 256>>>(cnt, n);
    k_count<<<e4b, 256>>>(ei, is64, cnt, e);
    k_dinv<<<nb, 256>>>(cnt, dinv, n);

    if (par) {
        cudaEventRecord(evA, 0);
        cudaStreamWaitEvent(s1, evA, 0);
        k_gemm128t<<<gemm_blocks, 256, SMEM_TC, s1>>>(x, W1, dinv, H, n);
        cudaEventRecord(evB, s1);
        // CSR build continues on stream 0, overlapped with GEMM-1
        k_scan_partial<<<scan_blocks, 256>>>(cnt, partials, n);
        k_scan_offsets<<<1, MAX_PARTIALS>>>(partials, rowptr, scan_blocks, n);
        k_scan_final<<<scan_blocks, 256>>>(cnt, partials, rowptr, cursor, n);
        k_fill<<<e4b, 256>>>(ei, is64, cursor, adj, e);
        cudaStreamWaitEvent(0, evB, 0);
    } else {
        k_scan_partial<<<scan_blocks, 256>>>(cnt, partials, n);
        k_scan_offsets<<<1, MAX_PARTIALS>>>(partials, rowptr, scan_blocks, n);
        k_scan_final<<<scan_blocks, 256>>>(cnt, partials, rowptr, cursor, n);
        k_fill<<<e4b, 256>>>(ei, is64, cursor, adj, e);
        k_gemm128t<<<gemm_blocks, 256, SMEM_TC>>>(x, W1, dinv, H, n);
    }

    // layer 1 aggregation (fp16 out)
    k_gather<<<gb, 256>>>(H, rowptr, adj, dinv, b1, (uint2*)B2, n, 1);

    // layer 2 (fp16 in/out)
    k_gemm128th<<<gemm_blocks, 256, SMEM_TC>>>(B2, W2, dinv, H, n);
    k_gather<<<gb, 256>>>(H, rowptr, adj, dinv, b2, (uint2*)B2, n, 0);

    // head + softmax (fp16 in)
    k_final_tc<<<gemm_blocks, 256, SMEM_FINAL>>>(B2, Wa, ba, out, n);
}